// round 7
// baseline (speedup 1.0000x reference)
#include <cuda_runtime.h>
#include <cstdint>

// Problem constants: B=2, S=2048, D=1024, H=16, HD=64
#define BB 2
#define SS 2048
#define DD 1024
#define HH 16
#define HDD 64
#define MROWS (BB * SS)   // 4096

__device__ float g_Q[BB * SS * DD];
__device__ float g_K[BB * SS * DD];
__device__ float g_V[BB * SS * DD];
__device__ float g_C[BB * SS * DD];

// ---------------------------------------------------------------------------
// tf32 helpers
// ---------------------------------------------------------------------------
__device__ __forceinline__ uint32_t f2tf32(float x) {
    uint32_t u;
    asm("cvt.rna.tf32.f32 %0, %1;" : "=r"(u) : "f"(x));
    return u;
}
__device__ __forceinline__ float tf32f(float x) {
    return __uint_as_float(f2tf32(x));
}

#define MMA_TF32(d, a, b)                                                    \
    asm volatile(                                                            \
        "mma.sync.aligned.m16n8k8.row.col.f32.tf32.tf32.f32 "                \
        "{%0,%1,%2,%3}, {%4,%5,%6,%7}, {%8,%9}, {%0,%1,%2,%3};"              \
        : "+f"((d)[0]), "+f"((d)[1]), "+f"((d)[2]), "+f"((d)[3])             \
        : "r"((a)[0]), "r"((a)[1]), "r"((a)[2]), "r"((a)[3]),                \
          "r"((b)[0]), "r"((b)[1]))

// ---------------------------------------------------------------------------
// tf32 tensor-core GEMM, double-buffered smem (ping-pong).
// C[M,N] = A[M,K] @ W[K,N] + bias[N]; M=4096, N=K=1024.
// CTA tile 128x128, BK=16, 256 threads = 8 warps, warp tile 64x32.
// One __syncthreads() per k-iteration: compute reads buf[cur] while each
// warp stores the prefetched tile into buf[cur^1] right after its compute.
// ---------------------------------------------------------------------------
#define AST 18   // padded row stride (16 + 2)

__global__ __launch_bounds__(256, 2)
void gemm_tf32(const float* __restrict__ A, const float* __restrict__ W,
               const float* __restrict__ bias, float* __restrict__ C)
{
    constexpr int K = 1024, N = 1024;
    __shared__ float As[2][128][AST];   // 2 x 9,216 B
    __shared__ float Bs[2][128][AST];   // 2 x 9,216 B   (total 36,864 B)

    const int tid  = threadIdx.x;
    const int lane = tid & 31;
    const int wid  = tid >> 5;
    const int warp_m = wid >> 2;          // 0..1 -> 64 rows
    const int warp_n = wid & 3;           // 0..3 -> 32 cols
    const int rowBase = blockIdx.y * 128;
    const int colBase = blockIdx.x * 128;

    // A loading: 128 rows x 16 k -> 2 float4/thread (one k8 group each)
    const int arow = tid >> 1;            // 0..127
    const int ag   = tid & 1;             // k8 group 0/1
    // B loading: 16 k-rows x 128 n -> 2 float4/thread
    const int brow = tid >> 4;            // k 0..15
    const int bcol = (tid & 15) * 4;      // n0 (second chunk at +64)

    const float* Ap = A + (size_t)(rowBase + arow) * K + ag * 8;
    const float* Wp = W + (size_t)brow * N + colBase + bcol;

    const int bg = brow >> 3;                                  // k8 group
    const int bp = 2 * (brow & 3) + (((brow & 7) >= 4) ? 1 : 0);
    const int bc = bg * 8 + bp;                                // permuted col

    float acc[4][4][4];
#pragma unroll
    for (int mt = 0; mt < 4; mt++)
#pragma unroll
        for (int nt = 0; nt < 4; nt++)
#pragma unroll
            for (int r = 0; r < 4; r++) acc[mt][nt][r] = 0.f;

    // ---- prologue: load tile 0 into buffer 0 ----
    float4 a0v = *(const float4*)(Ap);
    float4 a1v = *(const float4*)(Ap + 4);
    float4 b0v = *(const float4*)(Wp);
    float4 b1v = *(const float4*)(Wp + 64);

    {
        const int c0 = ag * 8;
        As[0][arow][c0 + 0] = tf32f(a0v.x);
        As[0][arow][c0 + 2] = tf32f(a0v.y);
        As[0][arow][c0 + 4] = tf32f(a0v.z);
        As[0][arow][c0 + 6] = tf32f(a0v.w);
        As[0][arow][c0 + 1] = tf32f(a1v.x);
        As[0][arow][c0 + 3] = tf32f(a1v.y);
        As[0][arow][c0 + 5] = tf32f(a1v.z);
        As[0][arow][c0 + 7] = tf32f(a1v.w);
        Bs[0][bcol + 0][bc] = tf32f(b0v.x);
        Bs[0][bcol + 1][bc] = tf32f(b0v.y);
        Bs[0][bcol + 2][bc] = tf32f(b0v.z);
        Bs[0][bcol + 3][bc] = tf32f(b0v.w);
        Bs[0][bcol + 64][bc] = tf32f(b1v.x);
        Bs[0][bcol + 65][bc] = tf32f(b1v.y);
        Bs[0][bcol + 66][bc] = tf32f(b1v.z);
        Bs[0][bcol + 67][bc] = tf32f(b1v.w);
    }
    __syncthreads();

    const int niter = K / 16;   // 64
    for (int kt = 0; kt < niter; kt++) {
        const int cur = kt & 1;
        const int nxt = cur ^ 1;

        // prefetch next tile into registers
        if (kt + 1 < niter) {
            const int ko = (kt + 1) * 16;
            a0v = *(const float4*)(Ap + ko);
            a1v = *(const float4*)(Ap + ko + 4);
            b0v = *(const float4*)(Wp + (size_t)ko * N);
            b1v = *(const float4*)(Wp + (size_t)ko * N + 64);
        }

        // ---- compute: two k8 steps from buf[cur] ----
#pragma unroll
        for (int s = 0; s < 2; s++) {
            uint32_t af[4][4];
            uint32_t bf[4][2];
            const int kc = s * 8 + 2 * (lane & 3);
#pragma unroll
            for (int mt = 0; mt < 4; mt++) {
                const int r = warp_m * 64 + mt * 16 + (lane >> 2);
                const float2 lo = *(const float2*)&As[cur][r][kc];
                const float2 hi = *(const float2*)&As[cur][r + 8][kc];
                af[mt][0] = __float_as_uint(lo.x);
                af[mt][2] = __float_as_uint(lo.y);
                af[mt][1] = __float_as_uint(hi.x);
                af[mt][3] = __float_as_uint(hi.y);
            }
#pragma unroll
            for (int nt = 0; nt < 4; nt++) {
                const int n = warp_n * 32 + nt * 8 + (lane >> 2);
                const float2 bb = *(const float2*)&Bs[cur][n][kc];
                bf[nt][0] = __float_as_uint(bb.x);
                bf[nt][1] = __float_as_uint(bb.y);
            }
#pragma unroll
            for (int mt = 0; mt < 4; mt++)
#pragma unroll
                for (int nt = 0; nt < 4; nt++)
                    MMA_TF32(acc[mt][nt], af[mt], bf[nt]);
        }

        // ---- store prefetched tile into buf[nxt]; single barrier ----
        if (kt + 1 < niter) {
            const int c0 = ag * 8;
            As[nxt][arow][c0 + 0] = tf32f(a0v.x);
            As[nxt][arow][c0 + 2] = tf32f(a0v.y);
            As[nxt][arow][c0 + 4] = tf32f(a0v.z);
            As[nxt][arow][c0 + 6] = tf32f(a0v.w);
            As[nxt][arow][c0 + 1] = tf32f(a1v.x);
            As[nxt][arow][c0 + 3] = tf32f(a1v.y);
            As[nxt][arow][c0 + 5] = tf32f(a1v.z);
            As[nxt][arow][c0 + 7] = tf32f(a1v.w);
            Bs[nxt][bcol + 0][bc] = tf32f(b0v.x);
            Bs[nxt][bcol + 1][bc] = tf32f(b0v.y);
            Bs[nxt][bcol + 2][bc] = tf32f(b0v.z);
            Bs[nxt][bcol + 3][bc] = tf32f(b0v.w);
            Bs[nxt][bcol + 64][bc] = tf32f(b1v.x);
            Bs[nxt][bcol + 65][bc] = tf32f(b1v.y);
            Bs[nxt][bcol + 66][bc] = tf32f(b1v.z);
            Bs[nxt][bcol + 67][bc] = tf32f(b1v.w);
            __syncthreads();
        }
    }

    // ---- epilogue: bias + store ----
#pragma unroll
    for (int mt = 0; mt < 4; mt++) {
        const int r = rowBase + warp_m * 64 + mt * 16 + (lane >> 2);
#pragma unroll
        for (int nt = 0; nt < 4; nt++) {
            const int c = colBase + warp_n * 32 + nt * 8 + (lane & 3) * 2;
            const float bi0 = bias[c], bi1 = bias[c + 1];
            float2 o0 = make_float2(acc[mt][nt][0] + bi0, acc[mt][nt][1] + bi1);
            float2 o1 = make_float2(acc[mt][nt][2] + bi0, acc[mt][nt][3] + bi1);
            *(float2*)&C[(size_t)r * N + c] = o0;
            *(float2*)&C[(size_t)(r + 8) * N + c] = o1;
        }
    }
}

// ---------------------------------------------------------------------------
// Tensor-core flash attention (tf32), occupancy-2 version.
// CTA = (b, h, 64-query tile), 128 threads = 4 warps; warp w owns q rows
// [16w, 16w+16). K tile 128 keys/iter, 16 iters over S=2048.
// smem = 106,496 B  ->  2 CTAs resident per SM (213 KB < 228 KB).
//
//   Ksm [128 keys][72]  : row = key, col = perm(d)      36,864 B
//   Vt  [64 d]   [136]  : col = perm(key)               34,816 B
//   Psm [64 q]   [136]  : probs, A-frag perm layout     34,816 B
// perm within each 8-group: pos(j) = 2*(j&3) + (j>>2).
// Softmax runs in exp2 domain: scores pre-scaled by log2(e)/sqrt(HD).
// ---------------------------------------------------------------------------
#define PKS 72
#define PVS 136
#define PPS 136
#define ATT_SMEM_BYTES ((128 * PKS + 64 * PVS + 64 * PPS) * 4)  // 106,496

#define QSCALE (0.125f * 1.44269504088896f)   // 1/sqrt(64) * log2(e)

__global__ __launch_bounds__(128, 2)
void attn_tc()
{
    extern __shared__ float sm[];
    float* Ksm = sm;                          // [128][PKS]
    float* Vt  = sm + 128 * PKS;              // [64][PVS]
    float* Psm = sm + 128 * PKS + 64 * PVS;   // [64][PPS]

    const int tid  = threadIdx.x;
    const int lane = tid & 31;
    const int w    = tid >> 5;                // 0..3
    const int b = blockIdx.z, h = blockIdx.y;
    const int q0 = blockIdx.x * 64;

    const float* Qg = g_Q + ((size_t)b * SS + q0) * DD + h * HDD;
    const float* Kg = g_K + (size_t)b * SS * DD + h * HDD;
    const float* Vg = g_V + (size_t)b * SS * DD + h * HDD;

    // Q staging mapping: 64 rows x 64 d by 128 threads (half row each)
    const int grow = tid >> 1;                // 0..63
    const int gcb  = (tid & 1) * 32;

    // ---- stage Q into Psm (perm layout), pre-scaled by log2e/sqrt(HD) ----
#pragma unroll
    for (int c = 0; c < 8; c++) {
        const int d0 = gcb + c * 4;
        const float4 v = *(const float4*)(Qg + (size_t)grow * DD + d0);
        const int g   = d0 >> 3;
        const int off = (d0 & 4) ? 1 : 0;
        float* p = Psm + grow * PPS + g * 8 + off;
        p[0] = tf32f(v.x * QSCALE);
        p[2] = tf32f(v.y * QSCALE);
        p[4] = tf32f(v.z * QSCALE);
        p[6] = tf32f(v.w * QSCALE);
    }
    __syncthreads();

    // ---- load Q A-fragments (warp-private rows) ----
    const int r = w * 16 + (lane >> 2);       // q row (and r+8), 0..63
    const int kc = 2 * (lane & 3);
    uint32_t qf[8][4];
#pragma unroll
    for (int s = 0; s < 8; s++) {
        const float2 lo = *(const float2*)&Psm[r * PPS + s * 8 + kc];
        const float2 hi = *(const float2*)&Psm[(r + 8) * PPS + s * 8 + kc];
        qf[s][0] = __float_as_uint(lo.x);
        qf[s][1] = __float_as_uint(hi.x);
        qf[s][2] = __float_as_uint(lo.y);
        qf[s][3] = __float_as_uint(hi.y);
    }

    // online softmax state (rows r and r+8), log2 domain
    float m0 = -1e30f, m1 = -1e30f, l0 = 0.f, l1 = 0.f;
    float oacc[8][4];
#pragma unroll
    for (int nt = 0; nt < 8; nt++)
#pragma unroll
        for (int i = 0; i < 4; i++) oacc[nt][i] = 0.f;

    const int pc0 = 2 * (kc & 3) + (kc >> 2);          // perm(2*(lane&3))
    const int pc1 = 2 * ((kc + 1) & 3) + ((kc + 1) >> 2);

    // K/V tile-load mapping: thread = key row (full 64-d row)
    const int kp = (tid & ~7) + 2 * (tid & 3) + ((tid & 7) >> 2);  // perm key

    for (int kt = 0; kt < SS / 128; kt++) {
        const int kr = kt * 128;
        __syncthreads();   // prev iteration's K/V reads complete

        // ---- load K tile -> Ksm[key][perm(d)] (key = tid) ----
#pragma unroll
        for (int c = 0; c < 16; c++) {
            const int d0 = c * 4;
            const float4 v = *(const float4*)(Kg + (size_t)(kr + tid) * DD + d0);
            const int g   = d0 >> 3;
            const int off = (d0 & 4) ? 1 : 0;
            float* p = Ksm + tid * PKS + g * 8 + off;
            p[0] = tf32f(v.x);
            p[2] = tf32f(v.y);
            p[4] = tf32f(v.z);
            p[6] = tf32f(v.w);
        }
        // ---- load V tile -> Vt[d][perm(key)] (transpose, key = tid) ----
#pragma unroll
        for (int c = 0; c < 16; c++) {
            const int d0 = c * 4;
            const float4 v = *(const float4*)(Vg + (size_t)(kr + tid) * DD + d0);
            Vt[(d0 + 0) * PVS + kp] = tf32f(v.x);
            Vt[(d0 + 1) * PVS + kp] = tf32f(v.y);
            Vt[(d0 + 2) * PVS + kp] = tf32f(v.z);
            Vt[(d0 + 3) * PVS + kp] = tf32f(v.w);
        }
        __syncthreads();

        // ---- scores: S[16 q][128 key] per warp (log2-domain) ----
        float sacc[16][4];
#pragma unroll
        for (int nt = 0; nt < 16; nt++)
#pragma unroll
            for (int i = 0; i < 4; i++) sacc[nt][i] = 0.f;

#pragma unroll
        for (int s = 0; s < 8; s++) {
#pragma unroll
            for (int nt = 0; nt < 16; nt++) {
                const float2 bv =
                    *(const float2*)&Ksm[(nt * 8 + (lane >> 2)) * PKS + s * 8 + kc];
                uint32_t bf[2] = {__float_as_uint(bv.x), __float_as_uint(bv.y)};
                MMA_TF32(sacc[nt], qf[s], bf);
            }
        }

        // ---- online softmax: dual accumulator chains + quad shfl ----
        float tma0 = -1e30f, tmb0 = -1e30f, tma1 = -1e30f, tmb1 = -1e30f;
#pragma unroll
        for (int nt = 0; nt < 16; nt += 2) {
            tma0 = fmaxf(tma0, fmaxf(sacc[nt][0], sacc[nt][1]));
            tmb0 = fmaxf(tmb0, fmaxf(sacc[nt + 1][0], sacc[nt + 1][1]));
            tma1 = fmaxf(tma1, fmaxf(sacc[nt][2], sacc[nt][3]));
            tmb1 = fmaxf(tmb1, fmaxf(sacc[nt + 1][2], sacc[nt + 1][3]));
        }
        float tm0 = fmaxf(tma0, tmb0);
        float tm1 = fmaxf(tma1, tmb1);
        tm0 = fmaxf(tm0, __shfl_xor_sync(0xffffffffu, tm0, 1));
        tm0 = fmaxf(tm0, __shfl_xor_sync(0xffffffffu, tm0, 2));
        tm1 = fmaxf(tm1, __shfl_xor_sync(0xffffffffu, tm1, 1));
        tm1 = fmaxf(tm1, __shfl_xor_sync(0xffffffffu, tm1, 2));

        const float nm0 = fmaxf(m0, tm0);
        const float nm1 = fmaxf(m1, tm1);
        const float cr0 = exp2f(m0 - nm0);
        const float cr1 = exp2f(m1 - nm1);

        float sa0 = 0.f, sb0 = 0.f, sa1 = 0.f, sb1 = 0.f;
#pragma unroll
        for (int nt = 0; nt < 16; nt++) {
            const float p00 = exp2f(sacc[nt][0] - nm0);
            const float p01 = exp2f(sacc[nt][1] - nm0);
            const float p10 = exp2f(sacc[nt][2] - nm1);
            const float p11 = exp2f(sacc[nt][3] - nm1);
            sa0 += p00; sb0 += p01;
            sa1 += p10; sb1 += p11;
            Psm[r * PPS + nt * 8 + pc0]       = tf32f(p00);
            Psm[r * PPS + nt * 8 + pc1]       = tf32f(p01);
            Psm[(r + 8) * PPS + nt * 8 + pc0] = tf32f(p10);
            Psm[(r + 8) * PPS + nt * 8 + pc1] = tf32f(p11);
        }
        float s0 = sa0 + sb0, s1 = sa1 + sb1;
        s0 += __shfl_xor_sync(0xffffffffu, s0, 1);
        s0 += __shfl_xor_sync(0xffffffffu, s0, 2);
        s1 += __shfl_xor_sync(0xffffffffu, s1, 1);
        s1 += __shfl_xor_sync(0xffffffffu, s1, 2);

        l0 = l0 * cr0 + s0;
        l1 = l1 * cr1 + s1;
        m0 = nm0;
        m1 = nm1;

#pragma unroll
        for (int nt = 0; nt < 8; nt++) {
            oacc[nt][0] *= cr0; oacc[nt][1] *= cr0;
            oacc[nt][2] *= cr1; oacc[nt][3] *= cr1;
        }
        __syncwarp();   // P rows are warp-private: order STS -> LDS in-warp

        // ---- PV: O[16 q][64 d] += P[16 q][128 key] @ V[128 key][64 d] ----
#pragma unroll
        for (int s2 = 0; s2 < 16; s2++) {
            const float2 plo = *(const float2*)&Psm[r * PPS + s2 * 8 + kc];
            const float2 phi = *(const float2*)&Psm[(r + 8) * PPS + s2 * 8 + kc];
            uint32_t pf[4];
            pf[0] = __float_as_uint(plo.x);
            pf[1] = __float_as_uint(phi.x);
            pf[2] = __float_as_uint(plo.y);
            pf[3] = __float_as_uint(phi.y);
#pragma unroll
            for (int nt = 0; nt < 8; nt++) {
                const float2 bv =
                    *(const float2*)&Vt[(nt * 8 + (lane >> 2)) * PVS + s2 * 8 + kc];
                uint32_t bf[2] = {__float_as_uint(bv.x), __float_as_uint(bv.y)};
                MMA_TF32(oacc[nt], pf, bf);
            }
        }
    }

    // ---- finalize: /l, write ctx ----
    const float inv0 = 1.f / l0;
    const float inv1 = 1.f / l1;
    float* Cg0 = g_C + ((size_t)b * SS + q0 + r) * DD + h * HDD;
    float* Cg1 = g_C + ((size_t)b * SS + q0 + r + 8) * DD + h * HDD;
#pragma unroll
    for (int nt = 0; nt < 8; nt++) {
        const int c = nt * 8 + kc;
        *(float2*)&Cg0[c] = make_float2(oacc[nt][0] * inv0, oacc[nt][1] * inv0);
        *(float2*)&Cg1[c] = make_float2(oacc[nt][2] * inv1, oacc[nt][3] * inv1);
    }
}

// ---------------------------------------------------------------------------
// Launch
// ---------------------------------------------------------------------------
extern "C" void kernel_launch(void* const* d_in, const int* in_sizes, int n_in,
                              void* d_out, int out_size)
{
    (void)in_sizes; (void)n_in; (void)out_size;
    const float* x  = (const float*)d_in[0];
    const float* Wq = (const float*)d_in[1];
    const float* bq = (const float*)d_in[2];
    const float* Wk = (const float*)d_in[3];
    const float* bk = (const float*)d_in[4];
    const float* Wv = (const float*)d_in[5];
    const float* bv = (const float*)d_in[6];
    const float* Wo = (const float*)d_in[7];
    const float* bo = (const float*)d_in[8];
    float* out = (float*)d_out;

    float *qp, *kp, *vp, *cp;
    cudaGetSymbolAddress((void**)&qp, g_Q);
    cudaGetSymbolAddress((void**)&kp, g_K);
    cudaGetSymbolAddress((void**)&vp, g_V);
    cudaGetSymbolAddress((void**)&cp, g_C);

    cudaFuncSetAttribute(attn_tc,
                         cudaFuncAttributeMaxDynamicSharedMemorySize,
                         ATT_SMEM_BYTES);

    const dim3 gblk(256);
    const dim3 ggrid(DD / 128, MROWS / 128);   // (8, 32)

    gemm_tf32<<<ggrid, gblk>>>(x, Wq, bq, qp);
    gemm_tf32<<<ggrid, gblk>>>(x, Wk, bk, kp);
    gemm_tf32<<<ggrid, gblk>>>(x, Wv, bv, vp);

    attn_tc<<<dim3(SS / 64, HH, BB), 128, ATT_SMEM_BYTES>>>();

    gemm_tf32<<<ggrid, gblk>>>(cp, Wo, bo, out);
}

// round 9
// speedup vs baseline: 1.1063x; 1.1063x over previous
#include <cuda_runtime.h>
#include <cstdint>

// Problem constants: B=2, S=2048, D=1024, H=16, HD=64
#define BB 2
#define SS 2048
#define DD 1024
#define HH 16
#define HDD 64
#define MROWS (BB * SS)   // 4096

__device__ float g_Q[BB * SS * DD];
__device__ float g_K[BB * SS * DD];
__device__ float g_V[BB * SS * DD];
__device__ float g_C[BB * SS * DD];

// ---------------------------------------------------------------------------
// tf32 / cp.async helpers
// ---------------------------------------------------------------------------
__device__ __forceinline__ uint32_t f2tf32(float x) {
    uint32_t u;
    asm("cvt.rna.tf32.f32 %0, %1;" : "=r"(u) : "f"(x));
    return u;
}
__device__ __forceinline__ float tf32f(float x) {
    return __uint_as_float(f2tf32(x));
}
__device__ __forceinline__ void cp16(uint32_t dst, const void* src) {
    asm volatile("cp.async.cg.shared.global [%0], [%1], 16;"
                 :: "r"(dst), "l"(src));
}

#define MMA_TF32(d, a, b)                                                    \
    asm volatile(                                                            \
        "mma.sync.aligned.m16n8k8.row.col.f32.tf32.tf32.f32 "                \
        "{%0,%1,%2,%3}, {%4,%5,%6,%7}, {%8,%9}, {%0,%1,%2,%3};"              \
        : "+f"((d)[0]), "+f"((d)[1]), "+f"((d)[2]), "+f"((d)[3])             \
        : "r"((a)[0]), "r"((a)[1]), "r"((a)[2]), "r"((a)[3]),                \
          "r"((b)[0]), "r"((b)[1]))

// ---------------------------------------------------------------------------
// tf32 tensor-core GEMM, double-buffered smem (round 7, unchanged)
// ---------------------------------------------------------------------------
#define AST 18

__global__ __launch_bounds__(256, 2)
void gemm_tf32(const float* __restrict__ A, const float* __restrict__ W,
               const float* __restrict__ bias, float* __restrict__ C)
{
    constexpr int K = 1024, N = 1024;
    __shared__ float As[2][128][AST];
    __shared__ float Bs[2][128][AST];

    const int tid  = threadIdx.x;
    const int lane = tid & 31;
    const int wid  = tid >> 5;
    const int warp_m = wid >> 2;
    const int warp_n = wid & 3;
    const int rowBase = blockIdx.y * 128;
    const int colBase = blockIdx.x * 128;

    const int arow = tid >> 1;
    const int ag   = tid & 1;
    const int brow = tid >> 4;
    const int bcol = (tid & 15) * 4;

    const float* Ap = A + (size_t)(rowBase + arow) * K + ag * 8;
    const float* Wp = W + (size_t)brow * N + colBase + bcol;

    const int bg = brow >> 3;
    const int bp = 2 * (brow & 3) + (((brow & 7) >= 4) ? 1 : 0);
    const int bc = bg * 8 + bp;

    float acc[4][4][4];
#pragma unroll
    for (int mt = 0; mt < 4; mt++)
#pragma unroll
        for (int nt = 0; nt < 4; nt++)
#pragma unroll
            for (int r = 0; r < 4; r++) acc[mt][nt][r] = 0.f;

    float4 a0v = *(const float4*)(Ap);
    float4 a1v = *(const float4*)(Ap + 4);
    float4 b0v = *(const float4*)(Wp);
    float4 b1v = *(const float4*)(Wp + 64);

    {
        const int c0 = ag * 8;
        As[0][arow][c0 + 0] = tf32f(a0v.x);
        As[0][arow][c0 + 2] = tf32f(a0v.y);
        As[0][arow][c0 + 4] = tf32f(a0v.z);
        As[0][arow][c0 + 6] = tf32f(a0v.w);
        As[0][arow][c0 + 1] = tf32f(a1v.x);
        As[0][arow][c0 + 3] = tf32f(a1v.y);
        As[0][arow][c0 + 5] = tf32f(a1v.z);
        As[0][arow][c0 + 7] = tf32f(a1v.w);
        Bs[0][bcol + 0][bc] = tf32f(b0v.x);
        Bs[0][bcol + 1][bc] = tf32f(b0v.y);
        Bs[0][bcol + 2][bc] = tf32f(b0v.z);
        Bs[0][bcol + 3][bc] = tf32f(b0v.w);
        Bs[0][bcol + 64][bc] = tf32f(b1v.x);
        Bs[0][bcol + 65][bc] = tf32f(b1v.y);
        Bs[0][bcol + 66][bc] = tf32f(b1v.z);
        Bs[0][bcol + 67][bc] = tf32f(b1v.w);
    }
    __syncthreads();

    const int niter = K / 16;
    for (int kt = 0; kt < niter; kt++) {
        const int cur = kt & 1;
        const int nxt = cur ^ 1;

        if (kt + 1 < niter) {
            const int ko = (kt + 1) * 16;
            a0v = *(const float4*)(Ap + ko);
            a1v = *(const float4*)(Ap + ko + 4);
            b0v = *(const float4*)(Wp + (size_t)ko * N);
            b1v = *(const float4*)(Wp + (size_t)ko * N + 64);
        }

#pragma unroll
        for (int s = 0; s < 2; s++) {
            uint32_t af[4][4];
            uint32_t bf[4][2];
            const int kc = s * 8 + 2 * (lane & 3);
#pragma unroll
            for (int mt = 0; mt < 4; mt++) {
                const int r = warp_m * 64 + mt * 16 + (lane >> 2);
                const float2 lo = *(const float2*)&As[cur][r][kc];
                const float2 hi = *(const float2*)&As[cur][r + 8][kc];
                af[mt][0] = __float_as_uint(lo.x);
                af[mt][2] = __float_as_uint(lo.y);
                af[mt][1] = __float_as_uint(hi.x);
                af[mt][3] = __float_as_uint(hi.y);
            }
#pragma unroll
            for (int nt = 0; nt < 4; nt++) {
                const int n = warp_n * 32 + nt * 8 + (lane >> 2);
                const float2 bb = *(const float2*)&Bs[cur][n][kc];
                bf[nt][0] = __float_as_uint(bb.x);
                bf[nt][1] = __float_as_uint(bb.y);
            }
#pragma unroll
            for (int mt = 0; mt < 4; mt++)
#pragma unroll
                for (int nt = 0; nt < 4; nt++)
                    MMA_TF32(acc[mt][nt], af[mt], bf[nt]);
        }

        if (kt + 1 < niter) {
            const int c0 = ag * 8;
            As[nxt][arow][c0 + 0] = tf32f(a0v.x);
            As[nxt][arow][c0 + 2] = tf32f(a0v.y);
            As[nxt][arow][c0 + 4] = tf32f(a0v.z);
            As[nxt][arow][c0 + 6] = tf32f(a0v.w);
            As[nxt][arow][c0 + 1] = tf32f(a1v.x);
            As[nxt][arow][c0 + 3] = tf32f(a1v.y);
            As[nxt][arow][c0 + 5] = tf32f(a1v.z);
            As[nxt][arow][c0 + 7] = tf32f(a1v.w);
            Bs[nxt][bcol + 0][bc] = tf32f(b0v.x);
            Bs[nxt][bcol + 1][bc] = tf32f(b0v.y);
            Bs[nxt][bcol + 2][bc] = tf32f(b0v.z);
            Bs[nxt][bcol + 3][bc] = tf32f(b0v.w);
            Bs[nxt][bcol + 64][bc] = tf32f(b1v.x);
            Bs[nxt][bcol + 65][bc] = tf32f(b1v.y);
            Bs[nxt][bcol + 66][bc] = tf32f(b1v.z);
            Bs[nxt][bcol + 67][bc] = tf32f(b1v.w);
            __syncthreads();
        }
    }

#pragma unroll
    for (int mt = 0; mt < 4; mt++) {
        const int r = rowBase + warp_m * 64 + mt * 16 + (lane >> 2);
#pragma unroll
        for (int nt = 0; nt < 4; nt++) {
            const int c = colBase + warp_n * 32 + nt * 8 + (lane & 3) * 2;
            const float bi0 = bias[c], bi1 = bias[c + 1];
            float2 o0 = make_float2(acc[mt][nt][0] + bi0, acc[mt][nt][1] + bi1);
            float2 o1 = make_float2(acc[mt][nt][2] + bi0, acc[mt][nt][3] + bi1);
            *(float2*)&C[(size_t)r * N + c] = o0;
            *(float2*)&C[(size_t)(r + 8) * N + c] = o1;
        }
    }
}

// ---------------------------------------------------------------------------
// Tensor-core flash attention (tf32) with cp.async double-buffered K/V.
// CTA = (b, h, 128-q tile), 256 threads = 8 warps; warp w owns q rows
// [16w, 16w+16). K tile 128 keys/iter, 16 iters over S=2048.
//
// smem (200,704 B):
//   K[2][128 keys][64 d]  raw fp32, row 256 B, chunk swizzle c^(r&7)   2x32 KB
//   V[2][128 keys][64 d]  raw fp32, row 256 B, chunk swizzle c^(2(r&3)) 2x32 KB
//   Psm [128 q][136]      probs in A-frag perm layout (also Q staging)  68 KB
// K/V converted to tf32 at fragment-load time (cvt.rna) — numerically
// identical to converting at store time. Swizzles chosen so both
// B-fragment access patterns are 32-bank conflict-free.
// ---------------------------------------------------------------------------
#define PPS 136
#define KVF 8192                    // floats per K or V buffer (128*64)
#define PSM_OFF 32768               // float offset of Psm (4 * 32 KB / 4)
#define ATT_SMEM_BYTES (4 * 32768 + 128 * PPS * 4)   // 200,704

#define QSCALE (0.125f * 1.44269504088896f)   // 1/sqrt(64) * log2(e)

__global__ __launch_bounds__(256, 1)
void attn_tc()
{
    extern __shared__ float sm[];
    float* Psm = sm + PSM_OFF;                // [128][PPS]

    const int tid  = threadIdx.x;
    const int lane = tid & 31;
    const int w    = tid >> 5;                // 0..7
    const int li   = lane >> 2;               // 0..7
    const int lj   = lane & 3;                // 0..3
    const int b = blockIdx.z, h = blockIdx.y;
    const int q0 = blockIdx.x * 128;

    const float* Qg = g_Q + ((size_t)b * SS + q0) * DD + h * HDD;
    const float* Kg = g_K + (size_t)b * SS * DD + h * HDD;
    const float* Vg = g_V + (size_t)b * SS * DD + h * HDD;

    const uint32_t smem_u32 = (uint32_t)__cvta_generic_to_shared(sm);

    // cp.async mapping: thread copies row irow, chunks [ihalf, ihalf+8)
    const int irow  = tid >> 1;               // 0..127
    const int ihalf = (tid & 1) * 8;          // 0 or 8
    const uint32_t ksw = (uint32_t)(irow & 7);         // K chunk swizzle
    const uint32_t vsw = (uint32_t)((irow & 3) << 1);  // V chunk swizzle
    const float* ksrc_base = Kg + (size_t)irow * DD + ihalf * 4;
    const float* vsrc_base = Vg + (size_t)irow * DD + ihalf * 4;
    const uint32_t krow_dst = smem_u32 + irow * 256;            // + buf*32768
    const uint32_t vrow_dst = smem_u32 + 65536 + irow * 256;    // + buf*32768

    // ---- issue tile 0 copies (overlap with Q staging) ----
    {
        const uint32_t kd = krow_dst;
        const uint32_t vd = vrow_dst;
#pragma unroll
        for (int q = 0; q < 8; q++) {
            const uint32_t ck = (uint32_t)(ihalf + q);
            cp16(kd + (((ck ^ ksw)) << 4), ksrc_base + q * 4);
            cp16(vd + (((ck ^ vsw)) << 4), vsrc_base + q * 4);
        }
        asm volatile("cp.async.commit_group;");
    }

    // ---- stage Q into Psm (perm layout), pre-scaled by log2e/sqrt(HD) ----
    const int grow = tid >> 1;
    const int gcb  = (tid & 1) * 32;
#pragma unroll
    for (int c = 0; c < 8; c++) {
        const int d0 = gcb + c * 4;
        const float4 v = *(const float4*)(Qg + (size_t)grow * DD + d0);
        const int g   = d0 >> 3;
        const int off = (d0 & 4) ? 1 : 0;
        float* p = Psm + grow * PPS + g * 8 + off;
        p[0] = tf32f(v.x * QSCALE);
        p[2] = tf32f(v.y * QSCALE);
        p[4] = tf32f(v.z * QSCALE);
        p[6] = tf32f(v.w * QSCALE);
    }
    __syncthreads();

    // ---- load Q A-fragments (warp-private rows) ----
    const int r = w * 16 + li;                // q row (and r+8), 0..127
    const int kc = 2 * lj;
    uint32_t qf[8][4];
#pragma unroll
    for (int s = 0; s < 8; s++) {
        const float2 lo = *(const float2*)&Psm[r * PPS + s * 8 + kc];
        const float2 hi = *(const float2*)&Psm[(r + 8) * PPS + s * 8 + kc];
        qf[s][0] = __float_as_uint(lo.x);
        qf[s][1] = __float_as_uint(hi.x);
        qf[s][2] = __float_as_uint(lo.y);
        qf[s][3] = __float_as_uint(hi.y);
    }

    // online softmax state (rows r and r+8), log2 domain
    float m0 = -1e30f, m1 = -1e30f, l0 = 0.f, l1 = 0.f;
    float oacc[8][4];
#pragma unroll
    for (int nt = 0; nt < 8; nt++)
#pragma unroll
        for (int i = 0; i < 4; i++) oacc[nt][i] = 0.f;

    const int pc0 = 2 * (kc & 3) + (kc >> 2);          // perm(2*lj)
    const int pc1 = 2 * ((kc + 1) & 3) + ((kc + 1) >> 2);

    for (int kt = 0; kt < SS / 128; kt++) {
        // ---- issue next tile's copies into buf[(kt+1)&1] ----
        if (kt + 1 < SS / 128) {
            const int ko = (kt + 1) * 128 * DD;
            const uint32_t bb = (uint32_t)((kt + 1) & 1) * 32768u;
            const uint32_t kd = krow_dst + bb;
            const uint32_t vd = vrow_dst + bb;
            const float* ks = ksrc_base + ko;
            const float* vs = vsrc_base + ko;
#pragma unroll
            for (int q = 0; q < 8; q++) {
                const uint32_t ck = (uint32_t)(ihalf + q);
                cp16(kd + ((ck ^ ksw) << 4), ks + q * 4);
                cp16(vd + ((ck ^ vsw) << 4), vs + q * 4);
            }
            asm volatile("cp.async.commit_group;");
            asm volatile("cp.async.wait_group 1;");
        } else {
            asm volatile("cp.async.wait_group 0;");
        }
        __syncthreads();   // tile kt's copies visible to all threads

        const float* Kb = sm + (kt & 1) * KVF;
        const float* Vb = sm + 16384 + (kt & 1) * KVF;

        // ---- scores: S[16 q][128 key] per warp (log2-domain) ----
        // B-frag: b0 = K[nt*8+li][s*8+lj], b1 = K[nt*8+li][s*8+lj+4]
        // smem idx = row*64 + ((chunk ^ (row&7)) * 4 + within); row&7 = li
        float sacc[16][4];
#pragma unroll
        for (int nt = 0; nt < 16; nt++)
#pragma unroll
            for (int i = 0; i < 4; i++) sacc[nt][i] = 0.f;

#pragma unroll
        for (int s = 0; s < 8; s++) {
            const int c0 = ((2 * s) ^ li) * 4 + lj;
            const int c1 = ((2 * s + 1) ^ li) * 4 + lj;
#pragma unroll
            for (int nt = 0; nt < 16; nt++) {
                const int rb = (nt * 8 + li) * 64;
                uint32_t bf[2];
                bf[0] = f2tf32(Kb[rb + c0]);
                bf[1] = f2tf32(Kb[rb + c1]);
                MMA_TF32(sacc[nt], qf[s], bf);
            }
        }

        // ---- online softmax: dual accumulator chains + quad shfl ----
        float tma0 = -1e30f, tmb0 = -1e30f, tma1 = -1e30f, tmb1 = -1e30f;
#pragma unroll
        for (int nt = 0; nt < 16; nt += 2) {
            tma0 = fmaxf(tma0, fmaxf(sacc[nt][0], sacc[nt][1]));
            tmb0 = fmaxf(tmb0, fmaxf(sacc[nt + 1][0], sacc[nt + 1][1]));
            tma1 = fmaxf(tma1, fmaxf(sacc[nt][2], sacc[nt][3]));
            tmb1 = fmaxf(tmb1, fmaxf(sacc[nt + 1][2], sacc[nt + 1][3]));
        }
        float tm0 = fmaxf(tma0, tmb0);
        float tm1 = fmaxf(tma1, tmb1);
        tm0 = fmaxf(tm0, __shfl_xor_sync(0xffffffffu, tm0, 1));
        tm0 = fmaxf(tm0, __shfl_xor_sync(0xffffffffu, tm0, 2));
        tm1 = fmaxf(tm1, __shfl_xor_sync(0xffffffffu, tm1, 1));
        tm1 = fmaxf(tm1, __shfl_xor_sync(0xffffffffu, tm1, 2));

        const float nm0 = fmaxf(m0, tm0);
        const float nm1 = fmaxf(m1, tm1);
        const float cr0 = exp2f(m0 - nm0);
        const float cr1 = exp2f(m1 - nm1);

        float sa0 = 0.f, sb0 = 0.f, sa1 = 0.f, sb1 = 0.f;
#pragma unroll
        for (int nt = 0; nt < 16; nt++) {
            const float p00 = exp2f(sacc[nt][0] - nm0);
            const float p01 = exp2f(sacc[nt][1] - nm0);
            const float p10 = exp2f(sacc[nt][2] - nm1);
            const float p11 = exp2f(sacc[nt][3] - nm1);
            sa0 += p00; sb0 += p01;
            sa1 += p10; sb1 += p11;
            Psm[r * PPS + nt * 8 + pc0]       = tf32f(p00);
            Psm[r * PPS + nt * 8 + pc1]       = tf32f(p01);
            Psm[(r + 8) * PPS + nt * 8 + pc0] = tf32f(p10);
            Psm[(r + 8) * PPS + nt * 8 + pc1] = tf32f(p11);
        }
        float s0 = sa0 + sb0, s1 = sa1 + sb1;
        s0 += __shfl_xor_sync(0xffffffffu, s0, 1);
        s0 += __shfl_xor_sync(0xffffffffu, s0, 2);
        s1 += __shfl_xor_sync(0xffffffffu, s1, 1);
        s1 += __shfl_xor_sync(0xffffffffu, s1, 2);

        l0 = l0 * cr0 + s0;
        l1 = l1 * cr1 + s1;
        m0 = nm0;
        m1 = nm1;

#pragma unroll
        for (int nt = 0; nt < 8; nt++) {
            oacc[nt][0] *= cr0; oacc[nt][1] *= cr0;
            oacc[nt][2] *= cr1; oacc[nt][3] *= cr1;
        }
        __syncwarp();   // P rows warp-private: order STS -> LDS in-warp

        // ---- PV: O[16 q][64 d] += P @ V ----
        // B-frag: b0 = V[s2*8+lj][nt*8+li], b1 = V[s2*8+lj+4][nt*8+li]
        // smem idx = row*64 + ((chunk ^ (2*(row&3))) * 4 + within); row&3 = lj
#pragma unroll
        for (int s2 = 0; s2 < 16; s2++) {
            const float2 plo = *(const float2*)&Psm[r * PPS + s2 * 8 + kc];
            const float2 phi = *(const float2*)&Psm[(r + 8) * PPS + s2 * 8 + kc];
            uint32_t pf[4];
            pf[0] = __float_as_uint(plo.x);
            pf[1] = __float_as_uint(phi.x);
            pf[2] = __float_as_uint(plo.y);
            pf[3] = __float_as_uint(phi.y);
            const int r0 = (s2 * 8 + lj) * 64;
            const int r1 = r0 + 4 * 64;
#pragma unroll
            for (int nt = 0; nt < 8; nt++) {
                const int cc = (((2 * nt + (li >> 2)) ^ (2 * lj)) << 2) + (li & 3);
                uint32_t bf[2];
                bf[0] = f2tf32(Vb[r0 + cc]);
                bf[1] = f2tf32(Vb[r1 + cc]);
                MMA_TF32(oacc[nt], pf, bf);
            }
        }
        __syncthreads();   // all reads of buf[kt&1] done before it is refilled
    }

    // ---- finalize: /l, write ctx ----
    const float inv0 = 1.f / l0;
    const float inv1 = 1.f / l1;
    float* Cg0 = g_C + ((size_t)b * SS + q0 + r) * DD + h * HDD;
    float* Cg1 = g_C + ((size_t)b * SS + q0 + r + 8) * DD + h * HDD;
#pragma unroll
    for (int nt = 0; nt < 8; nt++) {
        const int c = nt * 8 + kc;
        *(float2*)&Cg0[c] = make_float2(oacc[nt][0] * inv0, oacc[nt][1] * inv0);
        *(float2*)&Cg1[c] = make_float2(oacc[nt][2] * inv1, oacc[nt][3] * inv1);
    }
}

// ---------------------------------------------------------------------------
// Launch
// ---------------------------------------------------------------------------
extern "C" void kernel_launch(void* const* d_in, const int* in_sizes, int n_in,
                              void* d_out, int out_size)
{
    (void)in_sizes; (void)n_in; (void)out_size;
    const float* x  = (const float*)d_in[0];
    const float* Wq = (const float*)d_in[1];
    const float* bq = (const float*)d_in[2];
    const float* Wk = (const float*)d_in[3];
    const float* bk = (const float*)d_in[4];
    const float* Wv = (const float*)d_in[5];
    const float* bv = (const float*)d_in[6];
    const float* Wo = (const float*)d_in[7];
    const float* bo = (const float*)d_in[8];
    float* out = (float*)d_out;

    float *qp, *kp, *vp, *cp;
    cudaGetSymbolAddress((void**)&qp, g_Q);
    cudaGetSymbolAddress((void**)&kp, g_K);
    cudaGetSymbolAddress((void**)&vp, g_V);
    cudaGetSymbolAddress((void**)&cp, g_C);

    cudaFuncSetAttribute(attn_tc,
                         cudaFuncAttributeMaxDynamicSharedMemorySize,
                         ATT_SMEM_BYTES);

    const dim3 gblk(256);
    const dim3 ggrid(DD / 128, MROWS / 128);   // (8, 32)

    gemm_tf32<<<ggrid, gblk>>>(x, Wq, bq, qp);
    gemm_tf32<<<ggrid, gblk>>>(x, Wk, bk, kp);
    gemm_tf32<<<ggrid, gblk>>>(x, Wv, bv, vp);

    attn_tc<<<dim3(SS / 128, HH, BB), 256, ATT_SMEM_BYTES>>>();

    gemm_tf32<<<ggrid, gblk>>>(cp, Wo, bo, out);
}

// round 11
// speedup vs baseline: 1.3092x; 1.1834x over previous
#include <cuda_runtime.h>
#include <cstdint>

// Problem constants: B=2, S=2048, D=1024, H=16, HD=64
#define BB 2
#define SS 2048
#define DD 1024
#define HH 16
#define HDD 64
#define MROWS (BB * SS)   // 4096

__device__ float g_Q[BB * SS * DD];
__device__ float g_K[BB * SS * DD];
__device__ float g_V[BB * SS * DD];
__device__ float g_C[BB * SS * DD];

// ---------------------------------------------------------------------------
// tf32 / cp.async helpers
// ---------------------------------------------------------------------------
__device__ __forceinline__ uint32_t f2tf32(float x) {
    uint32_t u;
    asm("cvt.rna.tf32.f32 %0, %1;" : "=r"(u) : "f"(x));
    return u;
}
__device__ __forceinline__ float tf32f(float x) {
    return __uint_as_float(f2tf32(x));
}
__device__ __forceinline__ void cp16(uint32_t dst, const void* src) {
    asm volatile("cp.async.cg.shared.global [%0], [%1], 16;"
                 :: "r"(dst), "l"(src));
}

#define MMA_TF32(d, a, b)                                                    \
    asm volatile(                                                            \
        "mma.sync.aligned.m16n8k8.row.col.f32.tf32.tf32.f32 "                \
        "{%0,%1,%2,%3}, {%4,%5,%6,%7}, {%8,%9}, {%0,%1,%2,%3};"              \
        : "+f"((d)[0]), "+f"((d)[1]), "+f"((d)[2]), "+f"((d)[3])             \
        : "r"((a)[0]), "r"((a)[1]), "r"((a)[2]), "r"((a)[3]),                \
          "r"((b)[0]), "r"((b)[1]))

// ---------------------------------------------------------------------------
// tf32 tensor-core GEMM, 4-stage cp.async pipeline.
// C[M,N] = A[M,K] @ W[K,N] + bias[N]; M=4096, N=K=1024.
// CTA tile 128x128, BK=16, 256 threads = 8 warps, warp tile 64x32.
// smem per stage: A [128 rows][20 floats pad] = 10,240 B (pad -> 32 banks),
//                 B [16 k][128 n] chunk-swizzled c^((k&3)<<1) = 8,192 B.
// 4 stages = 73,728 B dynamic smem; occ 2. tf32 convert at fragment load.
// ROUND: round outputs to tf32 (for K/V so attention can skip the convert).
// ---------------------------------------------------------------------------
#define GSM_BYTES 73728
#define G_ASTG 2560     // floats per A stage (128*20)
#define G_BSTG 2048     // floats per B stage (16*128)
#define G_BOFF 10240    // float offset of B stages (4*2560)

template <bool ROUND>
__global__ __launch_bounds__(256, 2)
void gemm_tf32(const float* __restrict__ A, const float* __restrict__ W,
               const float* __restrict__ bias, float* __restrict__ C)
{
    constexpr int K = 1024, N = 1024;
    extern __shared__ float gsm[];

    const int tid  = threadIdx.x;
    const int lane = tid & 31;
    const int li   = lane >> 2;           // 0..7
    const int lj   = lane & 3;            // 0..3
    const int wid  = tid >> 5;
    const int warp_m = wid >> 2;          // 0..1
    const int warp_n = wid & 3;           // 0..3
    const int rowBase = blockIdx.y * 128;
    const int colBase = blockIdx.x * 128;

    const uint32_t smem_u32 = (uint32_t)__cvta_generic_to_shared(gsm);

    // copy mapping: A: 128 rows x 4 chunks (16B); thread -> row tid>>1, 2 chunks
    const int ar  = tid >> 1;
    const int ac  = (tid & 1) * 2;
    // B: 16 k-rows x 32 chunks; thread -> row tid>>4, 2 chunks
    const int br  = tid >> 4;
    const int bc0 = (tid & 15) * 2;
    const float* Asrc = A + (size_t)(rowBase + ar) * K + ac * 4;
    const float* Bsrc = W + (size_t)br * N + colBase + bc0 * 4;
    const uint32_t a_dst = smem_u32 + ar * 80 + ac * 16;
    const uint32_t bsw   = (uint32_t)((br & 3) << 1);
    const uint32_t b_dst = smem_u32 + G_BOFF * 4 + br * 512;
    const uint32_t bo0 = ((uint32_t)bc0 ^ bsw) << 4;
    const uint32_t bo1 = ((uint32_t)(bc0 + 1) ^ bsw) << 4;

#define G_ISSUE(t)                                                           \
    do {                                                                     \
        const int s_ = (t) & 3;                                              \
        const uint32_t ab_ = a_dst + s_ * (G_ASTG * 4);                      \
        const float* as_ = Asrc + (t) * 16;                                  \
        cp16(ab_, as_);                                                      \
        cp16(ab_ + 16, as_ + 4);                                             \
        const uint32_t bb_ = b_dst + s_ * (G_BSTG * 4);                      \
        const float* bs_ = Bsrc + (size_t)(t) * 16 * N;                      \
        cp16(bb_ + bo0, bs_);                                                \
        cp16(bb_ + bo1, bs_ + 4);                                            \
        asm volatile("cp.async.commit_group;");                              \
    } while (0)

    G_ISSUE(0);
    G_ISSUE(1);
    G_ISSUE(2);

    float acc[4][4][4];
#pragma unroll
    for (int mt = 0; mt < 4; mt++)
#pragma unroll
        for (int nt = 0; nt < 4; nt++)
#pragma unroll
            for (int r = 0; r < 4; r++) acc[mt][nt][r] = 0.f;

    const int niter = K / 16;   // 64
    for (int kt = 0; kt < niter; kt++) {
        if (kt < niter - 2)      asm volatile("cp.async.wait_group 2;");
        else if (kt == niter - 2) asm volatile("cp.async.wait_group 1;");
        else                      asm volatile("cp.async.wait_group 0;");
        __syncthreads();
        if (kt + 3 < niter) G_ISSUE(kt + 3);

        const float* Ast = gsm + (kt & 3) * G_ASTG;
        const float* Bst = gsm + G_BOFF + (kt & 3) * G_BSTG;

#pragma unroll
        for (int s = 0; s < 2; s++) {
            uint32_t af[4][4];
            uint32_t bf[4][2];
            const int colA = s * 8 + lj;
#pragma unroll
            for (int mt = 0; mt < 4; mt++) {
                const int r0 = (warp_m * 64 + mt * 16 + li) * 20;
                af[mt][0] = f2tf32(Ast[r0 + colA]);
                af[mt][1] = f2tf32(Ast[r0 + 160 + colA]);
                af[mt][2] = f2tf32(Ast[r0 + colA + 4]);
                af[mt][3] = f2tf32(Ast[r0 + 160 + colA + 4]);
            }
            const int rb0 = (s * 8 + lj) * 128;
#pragma unroll
            for (int nt = 0; nt < 4; nt++) {
                const int cidx =
                    (((warp_n * 8 + nt * 2 + (li >> 2)) ^ (lj << 1)) << 2) +
                    (li & 3);
                bf[nt][0] = f2tf32(Bst[rb0 + cidx]);
                bf[nt][1] = f2tf32(Bst[rb0 + 512 + cidx]);
            }
#pragma unroll
            for (int mt = 0; mt < 4; mt++)
#pragma unroll
                for (int nt = 0; nt < 4; nt++)
                    MMA_TF32(acc[mt][nt], af[mt], bf[nt]);
        }
    }

    // ---- epilogue: bias (+ optional tf32 rounding) + store ----
#pragma unroll
    for (int mt = 0; mt < 4; mt++) {
        const int r = rowBase + warp_m * 64 + mt * 16 + li;
#pragma unroll
        for (int nt = 0; nt < 4; nt++) {
            const int c = colBase + warp_n * 32 + nt * 8 + lj * 2;
            const float bi0 = bias[c], bi1 = bias[c + 1];
            float o00 = acc[mt][nt][0] + bi0, o01 = acc[mt][nt][1] + bi1;
            float o10 = acc[mt][nt][2] + bi0, o11 = acc[mt][nt][3] + bi1;
            if (ROUND) {
                o00 = tf32f(o00); o01 = tf32f(o01);
                o10 = tf32f(o10); o11 = tf32f(o11);
            }
            *(float2*)&C[(size_t)r * N + c]       = make_float2(o00, o01);
            *(float2*)&C[(size_t)(r + 8) * N + c] = make_float2(o10, o11);
        }
    }
}

// ---------------------------------------------------------------------------
// Tensor-core flash attention (tf32) with cp.async double-buffered K/V.
// CTA = (b, h, 128-q tile), 256 threads = 8 warps; warp w owns q rows
// [16w, 16w+16). K tile 128 keys/iter, 16 iters over S=2048.
// K/V are PRE-ROUNDED to tf32 by gemm_tf32<true> -> fragment loads are
// plain LDS (no cvt). Swizzles: K chunk c^(r&7), V chunk c^(2(r&3)).
// ---------------------------------------------------------------------------
#define PPS 136
#define KVF 8192                    // floats per K or V buffer (128*64)
#define PSM_OFF 32768               // float offset of Psm
#define ATT_SMEM_BYTES (4 * 32768 + 128 * PPS * 4)   // 200,704

#define QSCALE (0.125f * 1.44269504088896f)   // 1/sqrt(64) * log2(e)

__global__ __launch_bounds__(256, 1)
void attn_tc()
{
    extern __shared__ float sm[];
    float* Psm = sm + PSM_OFF;                // [128][PPS]

    const int tid  = threadIdx.x;
    const int lane = tid & 31;
    const int w    = tid >> 5;                // 0..7
    const int li   = lane >> 2;               // 0..7
    const int lj   = lane & 3;                // 0..3
    const int b = blockIdx.z, h = blockIdx.y;
    const int q0 = blockIdx.x * 128;

    const float* Qg = g_Q + ((size_t)b * SS + q0) * DD + h * HDD;
    const float* Kg = g_K + (size_t)b * SS * DD + h * HDD;
    const float* Vg = g_V + (size_t)b * SS * DD + h * HDD;

    const uint32_t smem_u32 = (uint32_t)__cvta_generic_to_shared(sm);

    // cp.async mapping: thread copies row irow, chunks [ihalf, ihalf+8)
    const int irow  = tid >> 1;               // 0..127
    const int ihalf = (tid & 1) * 8;          // 0 or 8
    const uint32_t ksw = (uint32_t)(irow & 7);         // K chunk swizzle
    const uint32_t vsw = (uint32_t)((irow & 3) << 1);  // V chunk swizzle
    const float* ksrc_base = Kg + (size_t)irow * DD + ihalf * 4;
    const float* vsrc_base = Vg + (size_t)irow * DD + ihalf * 4;
    const uint32_t krow_dst = smem_u32 + irow * 256;            // + buf*32768
    const uint32_t vrow_dst = smem_u32 + 65536 + irow * 256;    // + buf*32768

    // ---- issue tile 0 copies (overlap with Q staging) ----
    {
        const uint32_t kd = krow_dst;
        const uint32_t vd = vrow_dst;
#pragma unroll
        for (int q = 0; q < 8; q++) {
            const uint32_t ck = (uint32_t)(ihalf + q);
            cp16(kd + (((ck ^ ksw)) << 4), ksrc_base + q * 4);
            cp16(vd + (((ck ^ vsw)) << 4), vsrc_base + q * 4);
        }
        asm volatile("cp.async.commit_group;");
    }

    // ---- stage Q into Psm (perm layout), pre-scaled by log2e/sqrt(HD) ----
    const int grow = tid >> 1;
    const int gcb  = (tid & 1) * 32;
#pragma unroll
    for (int c = 0; c < 8; c++) {
        const int d0 = gcb + c * 4;
        const float4 v = *(const float4*)(Qg + (size_t)grow * DD + d0);
        const int g   = d0 >> 3;
        const int off = (d0 & 4) ? 1 : 0;
        float* p = Psm + grow * PPS + g * 8 + off;
        p[0] = tf32f(v.x * QSCALE);
        p[2] = tf32f(v.y * QSCALE);
        p[4] = tf32f(v.z * QSCALE);
        p[6] = tf32f(v.w * QSCALE);
    }
    __syncthreads();

    // ---- load Q A-fragments (warp-private rows) ----
    const int r = w * 16 + li;                // q row (and r+8), 0..127
    const int kc = 2 * lj;
    uint32_t qf[8][4];
#pragma unroll
    for (int s = 0; s < 8; s++) {
        const float2 lo = *(const float2*)&Psm[r * PPS + s * 8 + kc];
        const float2 hi = *(const float2*)&Psm[(r + 8) * PPS + s * 8 + kc];
        qf[s][0] = __float_as_uint(lo.x);
        qf[s][1] = __float_as_uint(hi.x);
        qf[s][2] = __float_as_uint(lo.y);
        qf[s][3] = __float_as_uint(hi.y);
    }

    // online softmax state (rows r and r+8), log2 domain
    float m0 = -1e30f, m1 = -1e30f, l0 = 0.f, l1 = 0.f;
    float oacc[8][4];
#pragma unroll
    for (int nt = 0; nt < 8; nt++)
#pragma unroll
        for (int i = 0; i < 4; i++) oacc[nt][i] = 0.f;

    const int pc0 = 2 * (kc & 3) + (kc >> 2);          // perm(2*lj)
    const int pc1 = 2 * ((kc + 1) & 3) + ((kc + 1) >> 2);

    for (int kt = 0; kt < SS / 128; kt++) {
        // ---- issue next tile's copies into buf[(kt+1)&1] ----
        if (kt + 1 < SS / 128) {
            const int ko = (kt + 1) * 128 * DD;
            const uint32_t bb = (uint32_t)((kt + 1) & 1) * 32768u;
            const uint32_t kd = krow_dst + bb;
            const uint32_t vd = vrow_dst + bb;
            const float* ks = ksrc_base + ko;
            const float* vs = vsrc_base + ko;
#pragma unroll
            for (int q = 0; q < 8; q++) {
                const uint32_t ck = (uint32_t)(ihalf + q);
                cp16(kd + ((ck ^ ksw) << 4), ks + q * 4);
                cp16(vd + ((ck ^ vsw) << 4), vs + q * 4);
            }
            asm volatile("cp.async.commit_group;");
            asm volatile("cp.async.wait_group 1;");
        } else {
            asm volatile("cp.async.wait_group 0;");
        }
        __syncthreads();   // tile kt's copies visible to all threads

        const float* Kb = sm + (kt & 1) * KVF;
        const float* Vb = sm + 16384 + (kt & 1) * KVF;

        // ---- scores: S[16 q][128 key] per warp (log2-domain) ----
        // K pre-rounded tf32 -> plain LDS + bitcast
        float sacc[16][4];
#pragma unroll
        for (int nt = 0; nt < 16; nt++)
#pragma unroll
            for (int i = 0; i < 4; i++) sacc[nt][i] = 0.f;

#pragma unroll
        for (int s = 0; s < 8; s++) {
            const int c0 = ((2 * s) ^ li) * 4 + lj;
            const int c1 = ((2 * s + 1) ^ li) * 4 + lj;
#pragma unroll
            for (int nt = 0; nt < 16; nt++) {
                const int rb = (nt * 8 + li) * 64;
                uint32_t bf[2];
                bf[0] = __float_as_uint(Kb[rb + c0]);
                bf[1] = __float_as_uint(Kb[rb + c1]);
                MMA_TF32(sacc[nt], qf[s], bf);
            }
        }

        // ---- online softmax: dual accumulator chains + quad shfl ----
        float tma0 = -1e30f, tmb0 = -1e30f, tma1 = -1e30f, tmb1 = -1e30f;
#pragma unroll
        for (int nt = 0; nt < 16; nt += 2) {
            tma0 = fmaxf(tma0, fmaxf(sacc[nt][0], sacc[nt][1]));
            tmb0 = fmaxf(tmb0, fmaxf(sacc[nt + 1][0], sacc[nt + 1][1]));
            tma1 = fmaxf(tma1, fmaxf(sacc[nt][2], sacc[nt][3]));
            tmb1 = fmaxf(tmb1, fmaxf(sacc[nt + 1][2], sacc[nt + 1][3]));
        }
        float tm0 = fmaxf(tma0, tmb0);
        float tm1 = fmaxf(tma1, tmb1);
        tm0 = fmaxf(tm0, __shfl_xor_sync(0xffffffffu, tm0, 1));
        tm0 = fmaxf(tm0, __shfl_xor_sync(0xffffffffu, tm0, 2));
        tm1 = fmaxf(tm1, __shfl_xor_sync(0xffffffffu, tm1, 1));
        tm1 = fmaxf(tm1, __shfl_xor_sync(0xffffffffu, tm1, 2));

        const float nm0 = fmaxf(m0, tm0);
        const float nm1 = fmaxf(m1, tm1);
        const float cr0 = exp2f(m0 - nm0);
        const float cr1 = exp2f(m1 - nm1);

        float sa0 = 0.f, sb0 = 0.f, sa1 = 0.f, sb1 = 0.f;
#pragma unroll
        for (int nt = 0; nt < 16; nt++) {
            const float p00 = exp2f(sacc[nt][0] - nm0);
            const float p01 = exp2f(sacc[nt][1] - nm0);
            const float p10 = exp2f(sacc[nt][2] - nm1);
            const float p11 = exp2f(sacc[nt][3] - nm1);
            sa0 += p00; sb0 += p01;
            sa1 += p10; sb1 += p11;
            Psm[r * PPS + nt * 8 + pc0]       = tf32f(p00);
            Psm[r * PPS + nt * 8 + pc1]       = tf32f(p01);
            Psm[(r + 8) * PPS + nt * 8 + pc0] = tf32f(p10);
            Psm[(r + 8) * PPS + nt * 8 + pc1] = tf32f(p11);
        }
        float s0 = sa0 + sb0, s1 = sa1 + sb1;
        s0 += __shfl_xor_sync(0xffffffffu, s0, 1);
        s0 += __shfl_xor_sync(0xffffffffu, s0, 2);
        s1 += __shfl_xor_sync(0xffffffffu, s1, 1);
        s1 += __shfl_xor_sync(0xffffffffu, s1, 2);

        l0 = l0 * cr0 + s0;
        l1 = l1 * cr1 + s1;
        m0 = nm0;
        m1 = nm1;

#pragma unroll
        for (int nt = 0; nt < 8; nt++) {
            oacc[nt][0] *= cr0; oacc[nt][1] *= cr0;
            oacc[nt][2] *= cr1; oacc[nt][3] *= cr1;
        }
        __syncwarp();   // P rows warp-private: order STS -> LDS in-warp

        // ---- PV: O[16 q][64 d] += P @ V ----
        // V pre-rounded tf32 -> plain LDS + bitcast
#pragma unroll
        for (int s2 = 0; s2 < 16; s2++) {
            const float2 plo = *(const float2*)&Psm[r * PPS + s2 * 8 + kc];
            const float2 phi = *(const float2*)&Psm[(r + 8) * PPS + s2 * 8 + kc];
            uint32_t pf[4];
            pf[0] = __float_as_uint(plo.x);
            pf[1] = __float_as_uint(phi.x);
            pf[2] = __float_as_uint(plo.y);
            pf[3] = __float_as_uint(phi.y);
            const int r0 = (s2 * 8 + lj) * 64;
            const int r1 = r0 + 4 * 64;
#pragma unroll
            for (int nt = 0; nt < 8; nt++) {
                const int cc = (((2 * nt + (li >> 2)) ^ (2 * lj)) << 2) + (li & 3);
                uint32_t bf[2];
                bf[0] = __float_as_uint(Vb[r0 + cc]);
                bf[1] = __float_as_uint(Vb[r1 + cc]);
                MMA_TF32(oacc[nt], pf, bf);
            }
        }
        __syncthreads();   // all reads of buf[kt&1] done before it is refilled
    }

    // ---- finalize: /l, write ctx ----
    const float inv0 = 1.f / l0;
    const float inv1 = 1.f / l1;
    float* Cg0 = g_C + ((size_t)b * SS + q0 + r) * DD + h * HDD;
    float* Cg1 = g_C + ((size_t)b * SS + q0 + r + 8) * DD + h * HDD;
#pragma unroll
    for (int nt = 0; nt < 8; nt++) {
        const int c = nt * 8 + kc;
        *(float2*)&Cg0[c] = make_float2(oacc[nt][0] * inv0, oacc[nt][1] * inv0);
        *(float2*)&Cg1[c] = make_float2(oacc[nt][2] * inv1, oacc[nt][3] * inv1);
    }
}

// ---------------------------------------------------------------------------
// Launch
// ---------------------------------------------------------------------------
extern "C" void kernel_launch(void* const* d_in, const int* in_sizes, int n_in,
                              void* d_out, int out_size)
{
    (void)in_sizes; (void)n_in; (void)out_size;
    const float* x  = (const float*)d_in[0];
    const float* Wq = (const float*)d_in[1];
    const float* bq = (const float*)d_in[2];
    const float* Wk = (const float*)d_in[3];
    const float* bk = (const float*)d_in[4];
    const float* Wv = (const float*)d_in[5];
    const float* bv = (const float*)d_in[6];
    const float* Wo = (const float*)d_in[7];
    const float* bo = (const float*)d_in[8];
    float* out = (float*)d_out;

    float *qp, *kp, *vp, *cp;
    cudaGetSymbolAddress((void**)&qp, g_Q);
    cudaGetSymbolAddress((void**)&kp, g_K);
    cudaGetSymbolAddress((void**)&vp, g_V);
    cudaGetSymbolAddress((void**)&cp, g_C);

    cudaFuncSetAttribute(gemm_tf32<false>,
                         cudaFuncAttributeMaxDynamicSharedMemorySize,
                         GSM_BYTES);
    cudaFuncSetAttribute(gemm_tf32<true>,
                         cudaFuncAttributeMaxDynamicSharedMemorySize,
                         GSM_BYTES);
    cudaFuncSetAttribute(attn_tc,
                         cudaFuncAttributeMaxDynamicSharedMemorySize,
                         ATT_SMEM_BYTES);

    const dim3 gblk(256);
    const dim3 ggrid(DD / 128, MROWS / 128);   // (8, 32)

    gemm_tf32<false><<<ggrid, gblk, GSM_BYTES>>>(x, Wq, bq, qp);
    gemm_tf32<true ><<<ggrid, gblk, GSM_BYTES>>>(x, Wk, bk, kp);
    gemm_tf32<true ><<<ggrid, gblk, GSM_BYTES>>>(x, Wv, bv, vp);

    attn_tc<<<dim3(SS / 128, HH, BB), 256, ATT_SMEM_BYTES>>>();

    gemm_tf32<false><<<ggrid, gblk, GSM_BYTES>>>(cp, Wo, bo, out);
}

// round 12
// speedup vs baseline: 1.3380x; 1.0220x over previous
#include <cuda_runtime.h>
#include <cstdint>

// Problem constants: B=2, S=2048, D=1024, H=16, HD=64
#define BB 2
#define SS 2048
#define DD 1024
#define HH 16
#define HDD 64
#define MROWS (BB * SS)   // 4096

__device__ float g_Q[BB * SS * DD];
__device__ float g_K[BB * SS * DD];
__device__ float g_V[BB * SS * DD];
__device__ float g_C[BB * SS * DD];

// ---------------------------------------------------------------------------
// tf32 / cp.async helpers
// ---------------------------------------------------------------------------
__device__ __forceinline__ uint32_t f2tf32(float x) {
    uint32_t u;
    asm("cvt.rna.tf32.f32 %0, %1;" : "=r"(u) : "f"(x));
    return u;
}
__device__ __forceinline__ float tf32f(float x) {
    return __uint_as_float(f2tf32(x));
}
__device__ __forceinline__ void cp16(uint32_t dst, const void* src) {
    asm volatile("cp.async.cg.shared.global [%0], [%1], 16;"
                 :: "r"(dst), "l"(src));
}

#define MMA_TF32(d, a, b)                                                    \
    asm volatile(                                                            \
        "mma.sync.aligned.m16n8k8.row.col.f32.tf32.tf32.f32 "                \
        "{%0,%1,%2,%3}, {%4,%5,%6,%7}, {%8,%9}, {%0,%1,%2,%3};"              \
        : "+f"((d)[0]), "+f"((d)[1]), "+f"((d)[2]), "+f"((d)[3])             \
        : "r"((a)[0]), "r"((a)[1]), "r"((a)[2]), "r"((a)[3]),                \
          "r"((b)[0]), "r"((b)[1]))

// ---------------------------------------------------------------------------
// tf32 tensor-core GEMM, 4-stage cp.async pipeline (round 11, unchanged)
// ---------------------------------------------------------------------------
#define GSM_BYTES 73728
#define G_ASTG 2560     // floats per A stage (128*20)
#define G_BSTG 2048     // floats per B stage (16*128)
#define G_BOFF 10240    // float offset of B stages (4*2560)

template <bool ROUND>
__global__ __launch_bounds__(256, 2)
void gemm_tf32(const float* __restrict__ A, const float* __restrict__ W,
               const float* __restrict__ bias, float* __restrict__ C)
{
    constexpr int K = 1024, N = 1024;
    extern __shared__ float gsm[];

    const int tid  = threadIdx.x;
    const int lane = tid & 31;
    const int li   = lane >> 2;           // 0..7
    const int lj   = lane & 3;            // 0..3
    const int wid  = tid >> 5;
    const int warp_m = wid >> 2;          // 0..1
    const int warp_n = wid & 3;           // 0..3
    const int rowBase = blockIdx.y * 128;
    const int colBase = blockIdx.x * 128;

    const uint32_t smem_u32 = (uint32_t)__cvta_generic_to_shared(gsm);

    const int ar  = tid >> 1;
    const int ac  = (tid & 1) * 2;
    const int br  = tid >> 4;
    const int bc0 = (tid & 15) * 2;
    const float* Asrc = A + (size_t)(rowBase + ar) * K + ac * 4;
    const float* Bsrc = W + (size_t)br * N + colBase + bc0 * 4;
    const uint32_t a_dst = smem_u32 + ar * 80 + ac * 16;
    const uint32_t bsw   = (uint32_t)((br & 3) << 1);
    const uint32_t b_dst = smem_u32 + G_BOFF * 4 + br * 512;
    const uint32_t bo0 = ((uint32_t)bc0 ^ bsw) << 4;
    const uint32_t bo1 = ((uint32_t)(bc0 + 1) ^ bsw) << 4;

#define G_ISSUE(t)                                                           \
    do {                                                                     \
        const int s_ = (t) & 3;                                              \
        const uint32_t ab_ = a_dst + s_ * (G_ASTG * 4);                      \
        const float* as_ = Asrc + (t) * 16;                                  \
        cp16(ab_, as_);                                                      \
        cp16(ab_ + 16, as_ + 4);                                             \
        const uint32_t bb_ = b_dst + s_ * (G_BSTG * 4);                      \
        const float* bs_ = Bsrc + (size_t)(t) * 16 * N;                      \
        cp16(bb_ + bo0, bs_);                                                \
        cp16(bb_ + bo1, bs_ + 4);                                            \
        asm volatile("cp.async.commit_group;");                              \
    } while (0)

    G_ISSUE(0);
    G_ISSUE(1);
    G_ISSUE(2);

    float acc[4][4][4];
#pragma unroll
    for (int mt = 0; mt < 4; mt++)
#pragma unroll
        for (int nt = 0; nt < 4; nt++)
#pragma unroll
            for (int r = 0; r < 4; r++) acc[mt][nt][r] = 0.f;

    const int niter = K / 16;   // 64
    for (int kt = 0; kt < niter; kt++) {
        if (kt < niter - 2)      asm volatile("cp.async.wait_group 2;");
        else if (kt == niter - 2) asm volatile("cp.async.wait_group 1;");
        else                      asm volatile("cp.async.wait_group 0;");
        __syncthreads();
        if (kt + 3 < niter) G_ISSUE(kt + 3);

        const float* Ast = gsm + (kt & 3) * G_ASTG;
        const float* Bst = gsm + G_BOFF + (kt & 3) * G_BSTG;

#pragma unroll
        for (int s = 0; s < 2; s++) {
            uint32_t af[4][4];
            uint32_t bf[4][2];
            const int colA = s * 8 + lj;
#pragma unroll
            for (int mt = 0; mt < 4; mt++) {
                const int r0 = (warp_m * 64 + mt * 16 + li) * 20;
                af[mt][0] = f2tf32(Ast[r0 + colA]);
                af[mt][1] = f2tf32(Ast[r0 + 160 + colA]);
                af[mt][2] = f2tf32(Ast[r0 + colA + 4]);
                af[mt][3] = f2tf32(Ast[r0 + 160 + colA + 4]);
            }
            const int rb0 = (s * 8 + lj) * 128;
#pragma unroll
            for (int nt = 0; nt < 4; nt++) {
                const int cidx =
                    (((warp_n * 8 + nt * 2 + (li >> 2)) ^ (lj << 1)) << 2) +
                    (li & 3);
                bf[nt][0] = f2tf32(Bst[rb0 + cidx]);
                bf[nt][1] = f2tf32(Bst[rb0 + 512 + cidx]);
            }
#pragma unroll
            for (int mt = 0; mt < 4; mt++)
#pragma unroll
                for (int nt = 0; nt < 4; nt++)
                    MMA_TF32(acc[mt][nt], af[mt], bf[nt]);
        }
    }

#pragma unroll
    for (int mt = 0; mt < 4; mt++) {
        const int r = rowBase + warp_m * 64 + mt * 16 + li;
#pragma unroll
        for (int nt = 0; nt < 4; nt++) {
            const int c = colBase + warp_n * 32 + nt * 8 + lj * 2;
            const float bi0 = bias[c], bi1 = bias[c + 1];
            float o00 = acc[mt][nt][0] + bi0, o01 = acc[mt][nt][1] + bi1;
            float o10 = acc[mt][nt][2] + bi0, o11 = acc[mt][nt][3] + bi1;
            if (ROUND) {
                o00 = tf32f(o00); o01 = tf32f(o01);
                o10 = tf32f(o10); o11 = tf32f(o11);
            }
            *(float2*)&C[(size_t)r * N + c]       = make_float2(o00, o01);
            *(float2*)&C[(size_t)(r + 8) * N + c] = make_float2(o10, o11);
        }
    }
}

// ---------------------------------------------------------------------------
// Tensor-core flash attention (tf32), cross-tile interleaved (FA2-style).
// CTA = (b, h, 128-q tile), 256 threads = 8 warps; warp w owns q rows
// [16w, 16w+16). 16 key-tiles of 128 over S=2048.
//
// Iteration kt fuses: scores-mma for tile kt+1 + PV-mma for tile kt
// (independent streams -> 2x mma ILP), then softmax(kt+1) as tail.
// cp.async group G_t = {K(t+2), V(t+1)} issued in iter t, consumed in
// iter t+1; buffers (2xK, 2xV) refilled one full iteration after their
// last read, behind the single per-iteration __syncthreads().
// K/V pre-rounded to tf32 by gemm_tf32<true>; swizzles as round 9/11.
// ---------------------------------------------------------------------------
#define PPS 136
#define KVF 8192                    // floats per K or V buffer (128*64)
#define PSM_OFF 32768               // float offset of Psm
#define ATT_SMEM_BYTES (4 * 32768 + 128 * PPS * 4)   // 200,704

#define QSCALE (0.125f * 1.44269504088896f)   // 1/sqrt(64) * log2(e)

__global__ __launch_bounds__(256, 1)
void attn_tc()
{
    extern __shared__ float sm[];
    float* Psm = sm + PSM_OFF;                // [128][PPS]

    const int tid  = threadIdx.x;
    const int lane = tid & 31;
    const int w    = tid >> 5;                // 0..7
    const int li   = lane >> 2;               // 0..7
    const int lj   = lane & 3;                // 0..3
    const int b = blockIdx.z, h = blockIdx.y;
    const int q0 = blockIdx.x * 128;

    const float* Qg = g_Q + ((size_t)b * SS + q0) * DD + h * HDD;
    const float* Kg = g_K + (size_t)b * SS * DD + h * HDD;
    const float* Vg = g_V + (size_t)b * SS * DD + h * HDD;

    const uint32_t smem_u32 = (uint32_t)__cvta_generic_to_shared(sm);

    // cp.async mapping: thread copies row irow, chunks [ihalf, ihalf+8)
    const int irow  = tid >> 1;               // 0..127
    const int ihalf = (tid & 1) * 8;          // 0 or 8
    const uint32_t ksw = (uint32_t)(irow & 7);         // K chunk swizzle
    const uint32_t vsw = (uint32_t)((irow & 3) << 1);  // V chunk swizzle
    const float* ksrc_base = Kg + (size_t)irow * DD + ihalf * 4;
    const float* vsrc_base = Vg + (size_t)irow * DD + ihalf * 4;
    const uint32_t krow_dst = smem_u32 + irow * 256;            // + buf*32768
    const uint32_t vrow_dst = smem_u32 + 65536 + irow * 256;    // + buf*32768

#define AK_ISSUE(t)                                                          \
    do {                                                                     \
        const uint32_t kd_ = krow_dst + (uint32_t)((t) & 1) * 32768u;        \
        const float* ks_ = ksrc_base + (t) * 128 * DD;                       \
        _Pragma("unroll")                                                    \
        for (int q_ = 0; q_ < 8; q_++) {                                     \
            const uint32_t ck_ = (uint32_t)(ihalf + q_);                     \
            cp16(kd_ + ((ck_ ^ ksw) << 4), ks_ + q_ * 4);                    \
        }                                                                    \
    } while (0)

#define AV_ISSUE(t)                                                          \
    do {                                                                     \
        const uint32_t vd_ = vrow_dst + (uint32_t)((t) & 1) * 32768u;        \
        const float* vs_ = vsrc_base + (t) * 128 * DD;                       \
        _Pragma("unroll")                                                    \
        for (int q_ = 0; q_ < 8; q_++) {                                     \
            const uint32_t ck_ = (uint32_t)(ihalf + q_);                     \
            cp16(vd_ + ((ck_ ^ vsw) << 4), vs_ + q_ * 4);                    \
        }                                                                    \
    } while (0)

    // ---- prologue copies: P0 = {K0}, P1 = {K1, V0} ----
    AK_ISSUE(0);
    asm volatile("cp.async.commit_group;");
    AK_ISSUE(1);
    AV_ISSUE(0);
    asm volatile("cp.async.commit_group;");

    // ---- stage Q into Psm (perm layout), pre-scaled by log2e/sqrt(HD) ----
    const int grow = tid >> 1;
    const int gcb  = (tid & 1) * 32;
#pragma unroll
    for (int c = 0; c < 8; c++) {
        const int d0 = gcb + c * 4;
        const float4 v = *(const float4*)(Qg + (size_t)grow * DD + d0);
        const int g   = d0 >> 3;
        const int off = (d0 & 4) ? 1 : 0;
        float* p = Psm + grow * PPS + g * 8 + off;
        p[0] = tf32f(v.x * QSCALE);
        p[2] = tf32f(v.y * QSCALE);
        p[4] = tf32f(v.z * QSCALE);
        p[6] = tf32f(v.w * QSCALE);
    }
    __syncthreads();
    // After this point ALL Psm traffic is warp-private (rows 16w..16w+16).

    // ---- load Q A-fragments ----
    const int r = w * 16 + li;                // q row (and r+8), 0..127
    const int kc = 2 * lj;
    uint32_t qf[8][4];
#pragma unroll
    for (int s = 0; s < 8; s++) {
        const float2 lo = *(const float2*)&Psm[r * PPS + s * 8 + kc];
        const float2 hi = *(const float2*)&Psm[(r + 8) * PPS + s * 8 + kc];
        qf[s][0] = __float_as_uint(lo.x);
        qf[s][1] = __float_as_uint(hi.x);
        qf[s][2] = __float_as_uint(lo.y);
        qf[s][3] = __float_as_uint(hi.y);
    }

    float m0 = -1e30f, m1 = -1e30f, l0 = 0.f, l1 = 0.f;
    float oacc[8][4];
#pragma unroll
    for (int nt = 0; nt < 8; nt++)
#pragma unroll
        for (int i = 0; i < 4; i++) oacc[nt][i] = 0.f;

    const int pc0 = 2 * (kc & 3) + (kc >> 2);
    const int pc1 = 2 * ((kc + 1) & 3) + ((kc + 1) >> 2);

    float sacc[16][4];

    // softmax over sacc -> update m/l, rescale oacc, store P to Psm
#define SOFTMAX_BLOCK()                                                      \
    do {                                                                     \
        float tma0 = -1e30f, tmb0 = -1e30f, tma1 = -1e30f, tmb1 = -1e30f;    \
        _Pragma("unroll")                                                    \
        for (int nt = 0; nt < 16; nt += 2) {                                 \
            tma0 = fmaxf(tma0, fmaxf(sacc[nt][0], sacc[nt][1]));             \
            tmb0 = fmaxf(tmb0, fmaxf(sacc[nt + 1][0], sacc[nt + 1][1]));     \
            tma1 = fmaxf(tma1, fmaxf(sacc[nt][2], sacc[nt][3]));             \
            tmb1 = fmaxf(tmb1, fmaxf(sacc[nt + 1][2], sacc[nt + 1][3]));     \
        }                                                                    \
        float tm0 = fmaxf(tma0, tmb0);                                       \
        float tm1 = fmaxf(tma1, tmb1);                                       \
        tm0 = fmaxf(tm0, __shfl_xor_sync(0xffffffffu, tm0, 1));              \
        tm0 = fmaxf(tm0, __shfl_xor_sync(0xffffffffu, tm0, 2));              \
        tm1 = fmaxf(tm1, __shfl_xor_sync(0xffffffffu, tm1, 1));              \
        tm1 = fmaxf(tm1, __shfl_xor_sync(0xffffffffu, tm1, 2));              \
        const float nm0 = fmaxf(m0, tm0);                                    \
        const float nm1 = fmaxf(m1, tm1);                                    \
        const float cr0 = exp2f(m0 - nm0);                                   \
        const float cr1 = exp2f(m1 - nm1);                                   \
        float sa0 = 0.f, sb0 = 0.f, sa1 = 0.f, sb1 = 0.f;                    \
        _Pragma("unroll")                                                    \
        for (int nt = 0; nt < 16; nt++) {                                    \
            const float p00 = exp2f(sacc[nt][0] - nm0);                      \
            const float p01 = exp2f(sacc[nt][1] - nm0);                      \
            const float p10 = exp2f(sacc[nt][2] - nm1);                      \
            const float p11 = exp2f(sacc[nt][3] - nm1);                      \
            sa0 += p00; sb0 += p01;                                          \
            sa1 += p10; sb1 += p11;                                          \
            Psm[r * PPS + nt * 8 + pc0]       = tf32f(p00);                  \
            Psm[r * PPS + nt * 8 + pc1]       = tf32f(p01);                  \
            Psm[(r + 8) * PPS + nt * 8 + pc0] = tf32f(p10);                  \
            Psm[(r + 8) * PPS + nt * 8 + pc1] = tf32f(p11);                  \
        }                                                                    \
        float ss0 = sa0 + sb0, ss1 = sa1 + sb1;                              \
        ss0 += __shfl_xor_sync(0xffffffffu, ss0, 1);                         \
        ss0 += __shfl_xor_sync(0xffffffffu, ss0, 2);                         \
        ss1 += __shfl_xor_sync(0xffffffffu, ss1, 1);                         \
        ss1 += __shfl_xor_sync(0xffffffffu, ss1, 2);                         \
        l0 = l0 * cr0 + ss0;                                                 \
        l1 = l1 * cr1 + ss1;                                                 \
        m0 = nm0;                                                            \
        m1 = nm1;                                                            \
        _Pragma("unroll")                                                    \
        for (int nt = 0; nt < 8; nt++) {                                     \
            oacc[nt][0] *= cr0; oacc[nt][1] *= cr0;                          \
            oacc[nt][2] *= cr1; oacc[nt][3] *= cr1;                          \
        }                                                                    \
        __syncwarp();                                                        \
    } while (0)

    // ---- prologue compute: scores(0) + softmax(0) ----
    asm volatile("cp.async.wait_group 1;");   // K0 arrived (this thread)
    __syncthreads();                          // K0 arrived (all threads)
    {
        const float* Kb = sm;                 // K buf 0
#pragma unroll
        for (int nt = 0; nt < 16; nt++)
#pragma unroll
            for (int i = 0; i < 4; i++) sacc[nt][i] = 0.f;
#pragma unroll
        for (int s = 0; s < 8; s++) {
            const int c0 = ((2 * s) ^ li) * 4 + lj;
            const int c1 = ((2 * s + 1) ^ li) * 4 + lj;
#pragma unroll
            for (int nt = 0; nt < 16; nt++) {
                const int rb = (nt * 8 + li) * 64;
                uint32_t bf[2];
                bf[0] = __float_as_uint(Kb[rb + c0]);
                bf[1] = __float_as_uint(Kb[rb + c1]);
                MMA_TF32(sacc[nt], qf[s], bf);
            }
        }
        SOFTMAX_BLOCK();                      // P(0) ready
    }

    // ---- main loop: iter kt fuses scores(kt+1) + PV(kt) ----
    for (int kt = 0; kt < 15; kt++) {
        asm volatile("cp.async.wait_group 0;");   // {K(kt+1), V(kt)} arrived
        __syncthreads();                          // ... for all threads

        // issue G_kt = {K(kt+2), V(kt+1)}
        if (kt + 2 < 16) AK_ISSUE(kt + 2);
        AV_ISSUE(kt + 1);
        asm volatile("cp.async.commit_group;");

        const float* Kb = sm + ((kt + 1) & 1) * KVF;
        const float* Vb = sm + 16384 + (kt & 1) * KVF;

#pragma unroll
        for (int nt = 0; nt < 16; nt++)
#pragma unroll
            for (int i = 0; i < 4; i++) sacc[nt][i] = 0.f;

        // fused: scores step s=u (tile kt+1)  +  PV steps s2=2u,2u+1 (tile kt)
#pragma unroll
        for (int u = 0; u < 8; u++) {
            const int c0 = ((2 * u) ^ li) * 4 + lj;
            const int c1 = ((2 * u + 1) ^ li) * 4 + lj;
#pragma unroll
            for (int nt = 0; nt < 16; nt++) {
                const int rb = (nt * 8 + li) * 64;
                uint32_t bf[2];
                bf[0] = __float_as_uint(Kb[rb + c0]);
                bf[1] = __float_as_uint(Kb[rb + c1]);
                MMA_TF32(sacc[nt], qf[u], bf);
            }
#pragma unroll
            for (int t2 = 0; t2 < 2; t2++) {
                const int s2 = 2 * u + t2;
                const float2 plo = *(const float2*)&Psm[r * PPS + s2 * 8 + kc];
                const float2 phi = *(const float2*)&Psm[(r + 8) * PPS + s2 * 8 + kc];
                uint32_t pf[4];
                pf[0] = __float_as_uint(plo.x);
                pf[1] = __float_as_uint(phi.x);
                pf[2] = __float_as_uint(plo.y);
                pf[3] = __float_as_uint(phi.y);
                const int r0 = (s2 * 8 + lj) * 64;
                const int r1 = r0 + 4 * 64;
#pragma unroll
                for (int nt = 0; nt < 8; nt++) {
                    const int cc =
                        (((2 * nt + (li >> 2)) ^ (2 * lj)) << 2) + (li & 3);
                    uint32_t bf[2];
                    bf[0] = __float_as_uint(Vb[r0 + cc]);
                    bf[1] = __float_as_uint(Vb[r1 + cc]);
                    MMA_TF32(oacc[nt], pf, bf);
                }
            }
        }

        SOFTMAX_BLOCK();   // softmax(kt+1): rescale oacc, store P(kt+1)
    }

    // ---- epilogue: PV(15) ----
    asm volatile("cp.async.wait_group 0;");   // V(15) arrived
    __syncthreads();
    {
        const float* Vb = sm + 16384 + (15 & 1) * KVF;
#pragma unroll
        for (int s2 = 0; s2 < 16; s2++) {
            const float2 plo = *(const float2*)&Psm[r * PPS + s2 * 8 + kc];
            const float2 phi = *(const float2*)&Psm[(r + 8) * PPS + s2 * 8 + kc];
            uint32_t pf[4];
            pf[0] = __float_as_uint(plo.x);
            pf[1] = __float_as_uint(phi.x);
            pf[2] = __float_as_uint(plo.y);
            pf[3] = __float_as_uint(phi.y);
            const int r0 = (s2 * 8 + lj) * 64;
            const int r1 = r0 + 4 * 64;
#pragma unroll
            for (int nt = 0; nt < 8; nt++) {
                const int cc = (((2 * nt + (li >> 2)) ^ (2 * lj)) << 2) + (li & 3);
                uint32_t bf[2];
                bf[0] = __float_as_uint(Vb[r0 + cc]);
                bf[1] = __float_as_uint(Vb[r1 + cc]);
                MMA_TF32(oacc[nt], pf, bf);
            }
        }
    }

    // ---- finalize: /l, write ctx ----
    const float inv0 = 1.f / l0;
    const float inv1 = 1.f / l1;
    float* Cg0 = g_C + ((size_t)b * SS + q0 + r) * DD + h * HDD;
    float* Cg1 = g_C + ((size_t)b * SS + q0 + r + 8) * DD + h * HDD;
#pragma unroll
    for (int nt = 0; nt < 8; nt++) {
        const int c = nt * 8 + kc;
        *(float2*)&Cg0[c] = make_float2(oacc[nt][0] * inv0, oacc[nt][1] * inv0);
        *(float2*)&Cg1[c] = make_float2(oacc[nt][2] * inv1, oacc[nt][3] * inv1);
    }
}

// ---------------------------------------------------------------------------
// Launch
// ---------------------------------------------------------------------------
extern "C" void kernel_launch(void* const* d_in, const int* in_sizes, int n_in,
                              void* d_out, int out_size)
{
    (void)in_sizes; (void)n_in; (void)out_size;
    const float* x  = (const float*)d_in[0];
    const float* Wq = (const float*)d_in[1];
    const float* bq = (const float*)d_in[2];
    const float* Wk = (const float*)d_in[3];
    const float* bk = (const float*)d_in[4];
    const float* Wv = (const float*)d_in[5];
    const float* bv = (const float*)d_in[6];
    const float* Wo = (const float*)d_in[7];
    const float* bo = (const float*)d_in[8];
    float* out = (float*)d_out;

    float *qp, *kp, *vp, *cp;
    cudaGetSymbolAddress((void**)&qp, g_Q);
    cudaGetSymbolAddress((void**)&kp, g_K);
    cudaGetSymbolAddress((void**)&vp, g_V);
    cudaGetSymbolAddress((void**)&cp, g_C);

    cudaFuncSetAttribute(gemm_tf32<false>,
                         cudaFuncAttributeMaxDynamicSharedMemorySize,
                         GSM_BYTES);
    cudaFuncSetAttribute(gemm_tf32<true>,
                         cudaFuncAttributeMaxDynamicSharedMemorySize,
                         GSM_BYTES);
    cudaFuncSetAttribute(attn_tc,
                         cudaFuncAttributeMaxDynamicSharedMemorySize,
                         ATT_SMEM_BYTES);

    const dim3 gblk(256);
    const dim3 ggrid(DD / 128, MROWS / 128);   // (8, 32)

    gemm_tf32<false><<<ggrid, gblk, GSM_BYTES>>>(x, Wq, bq, qp);
    gemm_tf32<true ><<<ggrid, gblk, GSM_BYTES>>>(x, Wk, bk, kp);
    gemm_tf32<true ><<<ggrid, gblk, GSM_BYTES>>>(x, Wv, bv, vp);

    attn_tc<<<dim3(SS / 128, HH, BB), 256, ATT_SMEM_BYTES>>>();

    gemm_tf32<false><<<ggrid, gblk, GSM_BYTES>>>(cp, Wo, bo, out);
}

// round 14
// speedup vs baseline: 1.4466x; 1.0812x over previous
#include <cuda_runtime.h>
#include <cstdint>

// Problem constants: B=2, S=2048, D=1024, H=16, HD=64
#define BB 2
#define SS 2048
#define DD 1024
#define HH 16
#define HDD 64
#define MROWS (BB * SS)   // 4096

__device__ float g_Q[BB * SS * DD];
__device__ float g_K[BB * SS * DD];
__device__ float g_V[BB * SS * DD];
__device__ float g_C[BB * SS * DD];

// ---------------------------------------------------------------------------
// tf32 / cp.async helpers
// ---------------------------------------------------------------------------
__device__ __forceinline__ uint32_t f2tf32(float x) {
    uint32_t u;
    asm("cvt.rna.tf32.f32 %0, %1;" : "=r"(u) : "f"(x));
    return u;
}
__device__ __forceinline__ float tf32f(float x) {
    return __uint_as_float(f2tf32(x));
}
__device__ __forceinline__ void cp16(uint32_t dst, const void* src) {
    asm volatile("cp.async.cg.shared.global [%0], [%1], 16;"
                 :: "r"(dst), "l"(src));
}

#define MMA_TF32(d, a, b)                                                    \
    asm volatile(                                                            \
        "mma.sync.aligned.m16n8k8.row.col.f32.tf32.tf32.f32 "                \
        "{%0,%1,%2,%3}, {%4,%5,%6,%7}, {%8,%9}, {%0,%1,%2,%3};"              \
        : "+f"((d)[0]), "+f"((d)[1]), "+f"((d)[2]), "+f"((d)[3])             \
        : "r"((a)[0]), "r"((a)[1]), "r"((a)[2]), "r"((a)[3]),                \
          "r"((b)[0]), "r"((b)[1]))

// ---------------------------------------------------------------------------
// tf32 tensor-core GEMM, 4-stage cp.async pipeline (round 11, unchanged)
// ---------------------------------------------------------------------------
#define GSM_BYTES 73728
#define G_ASTG 2560     // floats per A stage (128*20)
#define G_BSTG 2048     // floats per B stage (16*128)
#define G_BOFF 10240    // float offset of B stages (4*2560)

template <bool ROUND>
__global__ __launch_bounds__(256, 2)
void gemm_tf32(const float* __restrict__ A, const float* __restrict__ W,
               const float* __restrict__ bias, float* __restrict__ C)
{
    constexpr int K = 1024, N = 1024;
    extern __shared__ float gsm[];

    const int tid  = threadIdx.x;
    const int lane = tid & 31;
    const int li   = lane >> 2;           // 0..7
    const int lj   = lane & 3;            // 0..3
    const int wid  = tid >> 5;
    const int warp_m = wid >> 2;          // 0..1
    const int warp_n = wid & 3;           // 0..3
    const int rowBase = blockIdx.y * 128;
    const int colBase = blockIdx.x * 128;

    const uint32_t smem_u32 = (uint32_t)__cvta_generic_to_shared(gsm);

    const int ar  = tid >> 1;
    const int ac  = (tid & 1) * 2;
    const int br  = tid >> 4;
    const int bc0 = (tid & 15) * 2;
    const float* Asrc = A + (size_t)(rowBase + ar) * K + ac * 4;
    const float* Bsrc = W + (size_t)br * N + colBase + bc0 * 4;
    const uint32_t a_dst = smem_u32 + ar * 80 + ac * 16;
    const uint32_t bsw   = (uint32_t)((br & 3) << 1);
    const uint32_t b_dst = smem_u32 + G_BOFF * 4 + br * 512;
    const uint32_t bo0 = ((uint32_t)bc0 ^ bsw) << 4;
    const uint32_t bo1 = ((uint32_t)(bc0 + 1) ^ bsw) << 4;

#define G_ISSUE(t)                                                           \
    do {                                                                     \
        const int s_ = (t) & 3;                                              \
        const uint32_t ab_ = a_dst + s_ * (G_ASTG * 4);                      \
        const float* as_ = Asrc + (t) * 16;                                  \
        cp16(ab_, as_);                                                      \
        cp16(ab_ + 16, as_ + 4);                                             \
        const uint32_t bb_ = b_dst + s_ * (G_BSTG * 4);                      \
        const float* bs_ = Bsrc + (size_t)(t) * 16 * N;                      \
        cp16(bb_ + bo0, bs_);                                                \
        cp16(bb_ + bo1, bs_ + 4);                                            \
        asm volatile("cp.async.commit_group;");                              \
    } while (0)

    G_ISSUE(0);
    G_ISSUE(1);
    G_ISSUE(2);

    float acc[4][4][4];
#pragma unroll
    for (int mt = 0; mt < 4; mt++)
#pragma unroll
        for (int nt = 0; nt < 4; nt++)
#pragma unroll
            for (int r = 0; r < 4; r++) acc[mt][nt][r] = 0.f;

    const int niter = K / 16;   // 64
    for (int kt = 0; kt < niter; kt++) {
        if (kt < niter - 2)      asm volatile("cp.async.wait_group 2;");
        else if (kt == niter - 2) asm volatile("cp.async.wait_group 1;");
        else                      asm volatile("cp.async.wait_group 0;");
        __syncthreads();
        if (kt + 3 < niter) G_ISSUE(kt + 3);

        const float* Ast = gsm + (kt & 3) * G_ASTG;
        const float* Bst = gsm + G_BOFF + (kt & 3) * G_BSTG;

#pragma unroll
        for (int s = 0; s < 2; s++) {
            uint32_t af[4][4];
            uint32_t bf[4][2];
            const int colA = s * 8 + lj;
#pragma unroll
            for (int mt = 0; mt < 4; mt++) {
                const int r0 = (warp_m * 64 + mt * 16 + li) * 20;
                af[mt][0] = f2tf32(Ast[r0 + colA]);
                af[mt][1] = f2tf32(Ast[r0 + 160 + colA]);
                af[mt][2] = f2tf32(Ast[r0 + colA + 4]);
                af[mt][3] = f2tf32(Ast[r0 + 160 + colA + 4]);
            }
            const int rb0 = (s * 8 + lj) * 128;
#pragma unroll
            for (int nt = 0; nt < 4; nt++) {
                const int cidx =
                    (((warp_n * 8 + nt * 2 + (li >> 2)) ^ (lj << 1)) << 2) +
                    (li & 3);
                bf[nt][0] = f2tf32(Bst[rb0 + cidx]);
                bf[nt][1] = f2tf32(Bst[rb0 + 512 + cidx]);
            }
#pragma unroll
            for (int mt = 0; mt < 4; mt++)
#pragma unroll
                for (int nt = 0; nt < 4; nt++)
                    MMA_TF32(acc[mt][nt], af[mt], bf[nt]);
        }
    }

#pragma unroll
    for (int mt = 0; mt < 4; mt++) {
        const int r = rowBase + warp_m * 64 + mt * 16 + li;
#pragma unroll
        for (int nt = 0; nt < 4; nt++) {
            const int c = colBase + warp_n * 32 + nt * 8 + lj * 2;
            const float bi0 = bias[c], bi1 = bias[c + 1];
            float o00 = acc[mt][nt][0] + bi0, o01 = acc[mt][nt][1] + bi1;
            float o10 = acc[mt][nt][2] + bi0, o11 = acc[mt][nt][3] + bi1;
            if (ROUND) {
                o00 = tf32f(o00); o01 = tf32f(o01);
                o10 = tf32f(o10); o11 = tf32f(o11);
            }
            *(float2*)&C[(size_t)r * N + c]       = make_float2(o00, o01);
            *(float2*)&C[(size_t)(r + 8) * N + c] = make_float2(o10, o11);
        }
    }
}

// ---------------------------------------------------------------------------
// Tensor-core flash attention (tf32), register-resident P.
// CTA = (b, h, 128-q tile), 256 threads = 8 warps; warp w owns q rows
// [16w, 16w+16). 16 key-tiles of 128 over S=2048; triple-buffered K/V.
//
// k-slot pairing trick: mma k-slots (lj, lj+4) are fed d/key pair
// (2lj, 2lj+1). Dot products are order-invariant, and under this pairing
// the score C-fragment IS the PV A-fragment (a = {c0,c2,c1,c3}) -> P never
// touches smem. Q frags load once from gmem; K B-frags are single LDS.64
// (adjacent d-pair); V B-frags are plain LDS.32 from natural [key][d].
//
// smem: K bufs 3 x [128 rows][72 floats]  (stride 288 B, bank-exact LDS.64)
//       V bufs 3 x [128 rows][68 floats]  (stride 272 B, bank-exact LDS.32)
//       total 215,040 B. All smem writes via cp.async; 1 barrier per tile.
// ---------------------------------------------------------------------------
#define KST 72                       // K row stride (floats)
#define VST 68                       // V row stride (floats)
#define KSTG (128 * KST)             // 9216 floats per K stage
#define VSTG (128 * VST)             // 8704 floats per V stage
#define VOFF (3 * KSTG)              // 27648 float offset of V stages
#define ATT_SMEM_BYTES ((3 * KSTG + 3 * VSTG) * 4)   // 215,040

#define QSCALE (0.125f * 1.44269504088896f)   // 1/sqrt(64) * log2(e)

__global__ __launch_bounds__(256, 1)
void attn_tc()
{
    extern __shared__ float sm[];

    const int tid  = threadIdx.x;
    const int lane = tid & 31;
    const int w    = tid >> 5;                // 0..7
    const int li   = lane >> 2;               // 0..7
    const int lj   = lane & 3;                // 0..3
    const int b = blockIdx.z, h = blockIdx.y;
    const int q0 = blockIdx.x * 128;

    const float* Qg = g_Q + ((size_t)b * SS + q0) * DD + h * HDD;
    const float* Kg = g_K + (size_t)b * SS * DD + h * HDD;
    const float* Vg = g_V + (size_t)b * SS * DD + h * HDD;

    const uint32_t smem_u32 = (uint32_t)__cvta_generic_to_shared(sm);

    // cp.async mapping: thread copies row irow, chunks [ihalf, ihalf+8)
    const int irow  = tid >> 1;               // 0..127
    const int ihalf = (tid & 1) * 8;          // 0 or 8
    const float* ksrc_base = Kg + (size_t)irow * DD + ihalf * 4;
    const float* vsrc_base = Vg + (size_t)irow * DD + ihalf * 4;
    const uint32_t krow_dst = smem_u32 + irow * (KST * 4) + ihalf * 16;
    const uint32_t vrow_dst = smem_u32 + VOFF * 4 + irow * (VST * 4) + ihalf * 16;

#define AKV_ISSUE(t)                                                         \
    do {                                                                     \
        const int st_ = (t) % 3;                                             \
        const uint32_t kd_ = krow_dst + (uint32_t)st_ * (KSTG * 4);          \
        const uint32_t vd_ = vrow_dst + (uint32_t)st_ * (VSTG * 4);          \
        const float* ks_ = ksrc_base + (size_t)(t) * 128 * DD;               \
        const float* vs_ = vsrc_base + (size_t)(t) * 128 * DD;               \
        _Pragma("unroll")                                                    \
        for (int q_ = 0; q_ < 8; q_++) {                                     \
            cp16(kd_ + q_ * 16, ks_ + q_ * 4);                               \
            cp16(vd_ + q_ * 16, vs_ + q_ * 4);                               \
        }                                                                    \
        asm volatile("cp.async.commit_group;");                              \
    } while (0)

    // prologue: issue tiles 0, 1
    AKV_ISSUE(0);
    AKV_ISSUE(1);

    // ---- Q A-fragments straight from gmem (paired d: slots lj,lj+4 <-
    // d 2lj,2lj+1), scaled by log2e/sqrt(HD), tf32-rounded ----
    const int r  = w * 16 + li;               // q rows r, r+8
    const int kc = 2 * lj;
    uint32_t qf[8][4];
#pragma unroll
    for (int s = 0; s < 8; s++) {
        const float2 lo = *(const float2*)(Qg + (size_t)r * DD + s * 8 + kc);
        const float2 hi = *(const float2*)(Qg + (size_t)(r + 8) * DD + s * 8 + kc);
        qf[s][0] = f2tf32(lo.x * QSCALE);
        qf[s][1] = f2tf32(hi.x * QSCALE);
        qf[s][2] = f2tf32(lo.y * QSCALE);
        qf[s][3] = f2tf32(hi.y * QSCALE);
    }

    float m0 = -1e30f, m1 = -1e30f, l0 = 0.f, l1 = 0.f;
    float oacc[8][4];
#pragma unroll
    for (int nt = 0; nt < 8; nt++)
#pragma unroll
        for (int i = 0; i < 4; i++) oacc[nt][i] = 0.f;

    float sacc[16][4];

    for (int kt = 0; kt < 16; kt++) {
        if (kt < 15) asm volatile("cp.async.wait_group 1;");
        else         asm volatile("cp.async.wait_group 0;");
        __syncthreads();                      // tile kt visible to all
        if (kt + 2 < 16) AKV_ISSUE(kt + 2);   // stage (kt+2)%3 != kt%3

        const float* Kb = sm + (kt % 3) * KSTG;
        const float* Vb = sm + VOFF + (kt % 3) * VSTG;

        // ---- scores: S[16 q][128 key] per warp (log2-domain) ----
        // B-frag: keys nt*8+li; d-pair (s*8+2lj, +1) adjacent -> LDS.64
#pragma unroll
        for (int nt = 0; nt < 16; nt++)
#pragma unroll
            for (int i = 0; i < 4; i++) sacc[nt][i] = 0.f;
#pragma unroll
        for (int s = 0; s < 8; s++) {
            const int cofs = s * 8 + kc;
#pragma unroll
            for (int nt = 0; nt < 16; nt++) {
                const float2 kv =
                    *(const float2*)&Kb[(nt * 8 + li) * KST + cofs];
                uint32_t bf[2] = {__float_as_uint(kv.x), __float_as_uint(kv.y)};
                MMA_TF32(sacc[nt], qf[s], bf);
            }
        }

        // ---- online softmax in registers; exps written back into sacc ----
        {
            float tma0 = -1e30f, tmb0 = -1e30f, tma1 = -1e30f, tmb1 = -1e30f;
#pragma unroll
            for (int nt = 0; nt < 16; nt += 2) {
                tma0 = fmaxf(tma0, fmaxf(sacc[nt][0], sacc[nt][1]));
                tmb0 = fmaxf(tmb0, fmaxf(sacc[nt + 1][0], sacc[nt + 1][1]));
                tma1 = fmaxf(tma1, fmaxf(sacc[nt][2], sacc[nt][3]));
                tmb1 = fmaxf(tmb1, fmaxf(sacc[nt + 1][2], sacc[nt + 1][3]));
            }
            float tm0 = fmaxf(tma0, tmb0);
            float tm1 = fmaxf(tma1, tmb1);
            tm0 = fmaxf(tm0, __shfl_xor_sync(0xffffffffu, tm0, 1));
            tm0 = fmaxf(tm0, __shfl_xor_sync(0xffffffffu, tm0, 2));
            tm1 = fmaxf(tm1, __shfl_xor_sync(0xffffffffu, tm1, 1));
            tm1 = fmaxf(tm1, __shfl_xor_sync(0xffffffffu, tm1, 2));

            const float nm0 = fmaxf(m0, tm0);
            const float nm1 = fmaxf(m1, tm1);
            const float cr0 = exp2f(m0 - nm0);
            const float cr1 = exp2f(m1 - nm1);

            float sa0 = 0.f, sb0 = 0.f, sa1 = 0.f, sb1 = 0.f;
#pragma unroll
            for (int nt = 0; nt < 16; nt++) {
                const float p00 = exp2f(sacc[nt][0] - nm0);
                const float p01 = exp2f(sacc[nt][1] - nm0);
                const float p10 = exp2f(sacc[nt][2] - nm1);
                const float p11 = exp2f(sacc[nt][3] - nm1);
                sa0 += p00; sb0 += p01;
                sa1 += p10; sb1 += p11;
                sacc[nt][0] = tf32f(p00);
                sacc[nt][1] = tf32f(p01);
                sacc[nt][2] = tf32f(p10);
                sacc[nt][3] = tf32f(p11);
            }
            float ss0 = sa0 + sb0, ss1 = sa1 + sb1;
            ss0 += __shfl_xor_sync(0xffffffffu, ss0, 1);
            ss0 += __shfl_xor_sync(0xffffffffu, ss0, 2);
            ss1 += __shfl_xor_sync(0xffffffffu, ss1, 1);
            ss1 += __shfl_xor_sync(0xffffffffu, ss1, 2);

            l0 = l0 * cr0 + ss0;
            l1 = l1 * cr1 + ss1;
            m0 = nm0;
            m1 = nm1;

#pragma unroll
            for (int nt = 0; nt < 8; nt++) {
                oacc[nt][0] *= cr0; oacc[nt][1] *= cr0;
                oacc[nt][2] *= cr1; oacc[nt][3] *= cr1;
            }
        }

        // ---- PV: P A-frag = sacc (C->A identity); V B-frag from natural
        // [key][d]: b0 = V[s2*8+2lj][nt*8+li], b1 = next key ----
#pragma unroll
        for (int s2 = 0; s2 < 16; s2++) {
            uint32_t pf[4];
            pf[0] = __float_as_uint(sacc[s2][0]);
            pf[1] = __float_as_uint(sacc[s2][2]);
            pf[2] = __float_as_uint(sacc[s2][1]);
            pf[3] = __float_as_uint(sacc[s2][3]);
            const int vr0 = (s2 * 8 + kc) * VST;
#pragma unroll
            for (int nt = 0; nt < 8; nt++) {
                const int cc = nt * 8 + li;
                uint32_t bf[2];
                bf[0] = __float_as_uint(Vb[vr0 + cc]);
                bf[1] = __float_as_uint(Vb[vr0 + VST + cc]);
                MMA_TF32(oacc[nt], pf, bf);
            }
        }
    }

    // ---- finalize: /l, write ctx ----
    const float inv0 = 1.f / l0;
    const float inv1 = 1.f / l1;
    float* Cg0 = g_C + ((size_t)b * SS + q0 + r) * DD + h * HDD;
    float* Cg1 = g_C + ((size_t)b * SS + q0 + r + 8) * DD + h * HDD;
#pragma unroll
    for (int nt = 0; nt < 8; nt++) {
        const int c = nt * 8 + kc;
        *(float2*)&Cg0[c] = make_float2(oacc[nt][0] * inv0, oacc[nt][1] * inv0);
        *(float2*)&Cg1[c] = make_float2(oacc[nt][2] * inv1, oacc[nt][3] * inv1);
    }
}

// ---------------------------------------------------------------------------
// Launch
// ---------------------------------------------------------------------------
extern "C" void kernel_launch(void* const* d_in, const int* in_sizes, int n_in,
                              void* d_out, int out_size)
{
    (void)in_sizes; (void)n_in; (void)out_size;
    const float* x  = (const float*)d_in[0];
    const float* Wq = (const float*)d_in[1];
    const float* bq = (const float*)d_in[2];
    const float* Wk = (const float*)d_in[3];
    const float* bk = (const float*)d_in[4];
    const float* Wv = (const float*)d_in[5];
    const float* bv = (const float*)d_in[6];
    const float* Wo = (const float*)d_in[7];
    const float* bo = (const float*)d_in[8];
    float* out = (float*)d_out;

    float *qp, *kp, *vp, *cp;
    cudaGetSymbolAddress((void**)&qp, g_Q);
    cudaGetSymbolAddress((void**)&kp, g_K);
    cudaGetSymbolAddress((void**)&vp, g_V);
    cudaGetSymbolAddress((void**)&cp, g_C);

    cudaFuncSetAttribute(gemm_tf32<false>,
                         cudaFuncAttributeMaxDynamicSharedMemorySize,
                         GSM_BYTES);
    cudaFuncSetAttribute(gemm_tf32<true>,
                         cudaFuncAttributeMaxDynamicSharedMemorySize,
                         GSM_BYTES);
    cudaFuncSetAttribute(attn_tc,
                         cudaFuncAttributeMaxDynamicSharedMemorySize,
                         ATT_SMEM_BYTES);

    const dim3 gblk(256);
    const dim3 ggrid(DD / 128, MROWS / 128);   // (8, 32)

    gemm_tf32<false><<<ggrid, gblk, GSM_BYTES>>>(x, Wq, bq, qp);
    gemm_tf32<true ><<<ggrid, gblk, GSM_BYTES>>>(x, Wk, bk, kp);
    gemm_tf32<true ><<<ggrid, gblk, GSM_BYTES>>>(x, Wv, bv, vp);

    attn_tc<<<dim3(SS / 128, HH, BB), 256, ATT_SMEM_BYTES>>>();

    gemm_tf32<false><<<ggrid, gblk, GSM_BYTES>>>(cp, Wo, bo, out);
}

// round 15
// speedup vs baseline: 1.4714x; 1.0171x over previous
#include <cuda_runtime.h>
#include <cstdint>

// Problem constants: B=2, S=2048, D=1024, H=16, HD=64
#define BB 2
#define SS 2048
#define DD 1024
#define HH 16
#define HDD 64
#define MROWS (BB * SS)   // 4096

__device__ float g_Q[BB * SS * DD];
__device__ float g_K[BB * SS * DD];
__device__ float g_V[BB * SS * DD];
__device__ float g_C[BB * SS * DD];
// tf32-pre-rounded inputs
__device__ float g_Xr[MROWS * DD];
__device__ float g_Wqr[DD * DD];
__device__ float g_Wkr[DD * DD];
__device__ float g_Wvr[DD * DD];
__device__ float g_Wor[DD * DD];

// ---------------------------------------------------------------------------
// tf32 / cp.async helpers
// ---------------------------------------------------------------------------
__device__ __forceinline__ uint32_t f2tf32(float x) {
    uint32_t u;
    asm("cvt.rna.tf32.f32 %0, %1;" : "=r"(u) : "f"(x));
    return u;
}
__device__ __forceinline__ float tf32f(float x) {
    return __uint_as_float(f2tf32(x));
}
__device__ __forceinline__ void cp16(uint32_t dst, const void* src) {
    asm volatile("cp.async.cg.shared.global [%0], [%1], 16;"
                 :: "r"(dst), "l"(src));
}

#define MMA_TF32(d, a, b)                                                    \
    asm volatile(                                                            \
        "mma.sync.aligned.m16n8k8.row.col.f32.tf32.tf32.f32 "                \
        "{%0,%1,%2,%3}, {%4,%5,%6,%7}, {%8,%9}, {%0,%1,%2,%3};"              \
        : "+f"((d)[0]), "+f"((d)[1]), "+f"((d)[2]), "+f"((d)[3])             \
        : "r"((a)[0]), "r"((a)[1]), "r"((a)[2]), "r"((a)[3]),                \
          "r"((b)[0]), "r"((b)[1]))

// ---------------------------------------------------------------------------
// Pre-round to tf32 (RNA), float4-vectorized. dst[i] = tf32(src[i]).
// ---------------------------------------------------------------------------
__global__ __launch_bounds__(256)
void round_tf32_kernel(const float* __restrict__ src, float* __restrict__ dst,
                       int n4)
{
    const int i = blockIdx.x * blockDim.x + threadIdx.x;
    if (i < n4) {
        float4 v = ((const float4*)src)[i];
        v.x = tf32f(v.x); v.y = tf32f(v.y);
        v.z = tf32f(v.z); v.w = tf32f(v.w);
        ((float4*)dst)[i] = v;
    }
}

// ---------------------------------------------------------------------------
// tf32 tensor-core GEMM v3: 4-stage cp.async pipeline, pre-rounded inputs
// (NO cvt at fragment load), k-slot-paired fragments.
// C[M,N] = A[M,K] @ W[K,N] + bias[N]; M=4096, N=K=1024.
// CTA tile 128x128, BK=16, 256 threads = 8 warps, warp tile 64x32.
//
// k-slot pairing: mma slots (lj, lj+4) <- k pair (s*8+2lj, +1).
//   A frags: two LDS.64 (adjacent k) per mt; A row stride 24 floats ->
//            per half-warp bases 24*li mod 32 = {0,24,16,8}: bank-exact.
//   B frags: two LDS.32 per nt from [16 k][128 n] with chunk swizzle
//            c ^ (k&7): word mod 32 = (li&3) | bit2(li>>2^..) | (nt'^lj):
//            all 32 distinct per instruction.
// smem: A 4 x [128][24] = 49,152 B; B 4 x [16][128] = 32,768 B -> 81,920 B.
// ROUND: round outputs to tf32 (K/V for attention).
// ---------------------------------------------------------------------------
#define GSM_BYTES 81920
#define G_ASTG 3072     // floats per A stage (128*24)
#define G_BSTG 2048     // floats per B stage (16*128)
#define G_BOFF 12288    // float offset of B stages (4*3072)

template <bool ROUND>
__global__ __launch_bounds__(256, 2)
void gemm_tf32(const float* __restrict__ A, const float* __restrict__ W,
               const float* __restrict__ bias, float* __restrict__ C)
{
    constexpr int K = 1024, N = 1024;
    extern __shared__ float gsm[];

    const int tid  = threadIdx.x;
    const int lane = tid & 31;
    const int li   = lane >> 2;           // 0..7
    const int lj   = lane & 3;            // 0..3
    const int wid  = tid >> 5;
    const int warp_m = wid >> 2;          // 0..1
    const int warp_n = wid & 3;           // 0..3
    const int rowBase = blockIdx.y * 128;
    const int colBase = blockIdx.x * 128;

    const uint32_t smem_u32 = (uint32_t)__cvta_generic_to_shared(gsm);

    // copy mapping A: 128 rows x 4 chunks; thread -> row tid>>1, 2 chunks
    const int ar  = tid >> 1;
    const int ac  = (tid & 1) * 2;
    // copy mapping B: 16 k-rows x 32 chunks; thread -> k tid>>4, 2 chunks
    const int br  = tid >> 4;
    const int bc0 = (tid & 15) * 2;
    const float* Asrc = A + (size_t)(rowBase + ar) * K + ac * 4;
    const float* Bsrc = W + (size_t)br * N + colBase + bc0 * 4;
    const uint32_t a_dst = smem_u32 + ar * 96 + ac * 16;         // stride 24 fl
    const uint32_t bsw   = (uint32_t)(br & 7);                   // chunk swz
    const uint32_t b_dst = smem_u32 + G_BOFF * 4 + br * 512;
    const uint32_t bo0 = ((uint32_t)bc0 ^ bsw) << 4;
    const uint32_t bo1 = ((uint32_t)(bc0 + 1) ^ bsw) << 4;

#define G_ISSUE(t)                                                           \
    do {                                                                     \
        const int s_ = (t) & 3;                                              \
        const uint32_t ab_ = a_dst + s_ * (G_ASTG * 4);                      \
        const float* as_ = Asrc + (t) * 16;                                  \
        cp16(ab_, as_);                                                      \
        cp16(ab_ + 16, as_ + 4);                                             \
        const uint32_t bb_ = b_dst + s_ * (G_BSTG * 4);                      \
        const float* bs_ = Bsrc + (size_t)(t) * 16 * N;                      \
        cp16(bb_ + bo0, bs_);                                                \
        cp16(bb_ + bo1, bs_ + 4);                                            \
        asm volatile("cp.async.commit_group;");                              \
    } while (0)

    G_ISSUE(0);
    G_ISSUE(1);
    G_ISSUE(2);

    float acc[4][4][4];
#pragma unroll
    for (int mt = 0; mt < 4; mt++)
#pragma unroll
        for (int nt = 0; nt < 4; nt++)
#pragma unroll
            for (int r = 0; r < 4; r++) acc[mt][nt][r] = 0.f;

    // per-thread B fragment addressing constants
    const int chv = warp_n * 8 + (li >> 2);   // chunk base (n>>2 high part)
    const int wi  = li & 3;                   // word within chunk
    const int e0  = 2 * lj;                   // k0 & 7
    const int e1  = 2 * lj + 1;               // k1 & 7

    const int niter = K / 16;   // 64
    for (int kt = 0; kt < niter; kt++) {
        if (kt < niter - 2)      asm volatile("cp.async.wait_group 2;");
        else if (kt == niter - 2) asm volatile("cp.async.wait_group 1;");
        else                      asm volatile("cp.async.wait_group 0;");
        __syncthreads();
        if (kt + 3 < niter) G_ISSUE(kt + 3);

        const float* Ast = gsm + (kt & 3) * G_ASTG;
        const float* Bst = gsm + G_BOFF + (kt & 3) * G_BSTG;

#pragma unroll
        for (int s = 0; s < 2; s++) {
            const int k0 = s * 8 + e0;        // paired k: k0, k0+1
            uint32_t af[4][4];
            uint32_t bf[4][2];
#pragma unroll
            for (int mt = 0; mt < 4; mt++) {
                const int r0 = (warp_m * 64 + mt * 16 + li) * 24;
                const float2 alo = *(const float2*)&Ast[r0 + k0];
                const float2 ahi = *(const float2*)&Ast[r0 + 192 + k0];
                af[mt][0] = __float_as_uint(alo.x);
                af[mt][1] = __float_as_uint(ahi.x);
                af[mt][2] = __float_as_uint(alo.y);
                af[mt][3] = __float_as_uint(ahi.y);
            }
            const int rb0 = k0 * 128;
#pragma unroll
            for (int nt = 0; nt < 4; nt++) {
                const int ch = chv + nt * 2;
                bf[nt][0] = __float_as_uint(Bst[rb0 + ((ch ^ e0) << 2) + wi]);
                bf[nt][1] = __float_as_uint(
                    Bst[rb0 + 128 + ((ch ^ e1) << 2) + wi]);
            }
#pragma unroll
            for (int mt = 0; mt < 4; mt++)
#pragma unroll
                for (int nt = 0; nt < 4; nt++)
                    MMA_TF32(acc[mt][nt], af[mt], bf[nt]);
        }
    }

    // ---- epilogue: bias (+ optional tf32 rounding) + store ----
#pragma unroll
    for (int mt = 0; mt < 4; mt++) {
        const int r = rowBase + warp_m * 64 + mt * 16 + li;
#pragma unroll
        for (int nt = 0; nt < 4; nt++) {
            const int c = colBase + warp_n * 32 + nt * 8 + lj * 2;
            const float bi0 = bias[c], bi1 = bias[c + 1];
            float o00 = acc[mt][nt][0] + bi0, o01 = acc[mt][nt][1] + bi1;
            float o10 = acc[mt][nt][2] + bi0, o11 = acc[mt][nt][3] + bi1;
            if (ROUND) {
                o00 = tf32f(o00); o01 = tf32f(o01);
                o10 = tf32f(o10); o11 = tf32f(o11);
            }
            *(float2*)&C[(size_t)r * N + c]       = make_float2(o00, o01);
            *(float2*)&C[(size_t)(r + 8) * N + c] = make_float2(o10, o11);
        }
    }
}

// ---------------------------------------------------------------------------
// Tensor-core flash attention (tf32), register-resident P (round 14),
// now writing ctx tf32-rounded (so the Wo GEMM needs no cvt).
// ---------------------------------------------------------------------------
#define KST 72                       // K row stride (floats)
#define VST 68                       // V row stride (floats)
#define KSTG (128 * KST)             // 9216 floats per K stage
#define VSTG (128 * VST)             // 8704 floats per V stage
#define VOFF (3 * KSTG)              // 27648 float offset of V stages
#define ATT_SMEM_BYTES ((3 * KSTG + 3 * VSTG) * 4)   // 215,040

#define QSCALE (0.125f * 1.44269504088896f)   // 1/sqrt(64) * log2(e)

__global__ __launch_bounds__(256, 1)
void attn_tc()
{
    extern __shared__ float sm[];

    const int tid  = threadIdx.x;
    const int lane = tid & 31;
    const int w    = tid >> 5;                // 0..7
    const int li   = lane >> 2;               // 0..7
    const int lj   = lane & 3;                // 0..3
    const int b = blockIdx.z, h = blockIdx.y;
    const int q0 = blockIdx.x * 128;

    const float* Qg = g_Q + ((size_t)b * SS + q0) * DD + h * HDD;
    const float* Kg = g_K + (size_t)b * SS * DD + h * HDD;
    const float* Vg = g_V + (size_t)b * SS * DD + h * HDD;

    const uint32_t smem_u32 = (uint32_t)__cvta_generic_to_shared(sm);

    const int irow  = tid >> 1;               // 0..127
    const int ihalf = (tid & 1) * 8;          // 0 or 8
    const float* ksrc_base = Kg + (size_t)irow * DD + ihalf * 4;
    const float* vsrc_base = Vg + (size_t)irow * DD + ihalf * 4;
    const uint32_t krow_dst = smem_u32 + irow * (KST * 4) + ihalf * 16;
    const uint32_t vrow_dst = smem_u32 + VOFF * 4 + irow * (VST * 4) + ihalf * 16;

#define AKV_ISSUE(t)                                                         \
    do {                                                                     \
        const int st_ = (t) % 3;                                             \
        const uint32_t kd_ = krow_dst + (uint32_t)st_ * (KSTG * 4);          \
        const uint32_t vd_ = vrow_dst + (uint32_t)st_ * (VSTG * 4);          \
        const float* ks_ = ksrc_base + (size_t)(t) * 128 * DD;               \
        const float* vs_ = vsrc_base + (size_t)(t) * 128 * DD;               \
        _Pragma("unroll")                                                    \
        for (int q_ = 0; q_ < 8; q_++) {                                     \
            cp16(kd_ + q_ * 16, ks_ + q_ * 4);                               \
            cp16(vd_ + q_ * 16, vs_ + q_ * 4);                               \
        }                                                                    \
        asm volatile("cp.async.commit_group;");                              \
    } while (0)

    AKV_ISSUE(0);
    AKV_ISSUE(1);

    const int r  = w * 16 + li;               // q rows r, r+8
    const int kc = 2 * lj;
    uint32_t qf[8][4];
#pragma unroll
    for (int s = 0; s < 8; s++) {
        const float2 lo = *(const float2*)(Qg + (size_t)r * DD + s * 8 + kc);
        const float2 hi = *(const float2*)(Qg + (size_t)(r + 8) * DD + s * 8 + kc);
        qf[s][0] = f2tf32(lo.x * QSCALE);
        qf[s][1] = f2tf32(hi.x * QSCALE);
        qf[s][2] = f2tf32(lo.y * QSCALE);
        qf[s][3] = f2tf32(hi.y * QSCALE);
    }

    float m0 = -1e30f, m1 = -1e30f, l0 = 0.f, l1 = 0.f;
    float oacc[8][4];
#pragma unroll
    for (int nt = 0; nt < 8; nt++)
#pragma unroll
        for (int i = 0; i < 4; i++) oacc[nt][i] = 0.f;

    float sacc[16][4];

    for (int kt = 0; kt < 16; kt++) {
        if (kt < 15) asm volatile("cp.async.wait_group 1;");
        else         asm volatile("cp.async.wait_group 0;");
        __syncthreads();
        if (kt + 2 < 16) AKV_ISSUE(kt + 2);

        const float* Kb = sm + (kt % 3) * KSTG;
        const float* Vb = sm + VOFF + (kt % 3) * VSTG;

#pragma unroll
        for (int nt = 0; nt < 16; nt++)
#pragma unroll
            for (int i = 0; i < 4; i++) sacc[nt][i] = 0.f;
#pragma unroll
        for (int s = 0; s < 8; s++) {
            const int cofs = s * 8 + kc;
#pragma unroll
            for (int nt = 0; nt < 16; nt++) {
                const float2 kv =
                    *(const float2*)&Kb[(nt * 8 + li) * KST + cofs];
                uint32_t bf[2] = {__float_as_uint(kv.x), __float_as_uint(kv.y)};
                MMA_TF32(sacc[nt], qf[s], bf);
            }
        }

        {
            float tma0 = -1e30f, tmb0 = -1e30f, tma1 = -1e30f, tmb1 = -1e30f;
#pragma unroll
            for (int nt = 0; nt < 16; nt += 2) {
                tma0 = fmaxf(tma0, fmaxf(sacc[nt][0], sacc[nt][1]));
                tmb0 = fmaxf(tmb0, fmaxf(sacc[nt + 1][0], sacc[nt + 1][1]));
                tma1 = fmaxf(tma1, fmaxf(sacc[nt][2], sacc[nt][3]));
                tmb1 = fmaxf(tmb1, fmaxf(sacc[nt + 1][2], sacc[nt + 1][3]));
            }
            float tm0 = fmaxf(tma0, tmb0);
            float tm1 = fmaxf(tma1, tmb1);
            tm0 = fmaxf(tm0, __shfl_xor_sync(0xffffffffu, tm0, 1));
            tm0 = fmaxf(tm0, __shfl_xor_sync(0xffffffffu, tm0, 2));
            tm1 = fmaxf(tm1, __shfl_xor_sync(0xffffffffu, tm1, 1));
            tm1 = fmaxf(tm1, __shfl_xor_sync(0xffffffffu, tm1, 2));

            const float nm0 = fmaxf(m0, tm0);
            const float nm1 = fmaxf(m1, tm1);
            const float cr0 = exp2f(m0 - nm0);
            const float cr1 = exp2f(m1 - nm1);

            float sa0 = 0.f, sb0 = 0.f, sa1 = 0.f, sb1 = 0.f;
#pragma unroll
            for (int nt = 0; nt < 16; nt++) {
                const float p00 = exp2f(sacc[nt][0] - nm0);
                const float p01 = exp2f(sacc[nt][1] - nm0);
                const float p10 = exp2f(sacc[nt][2] - nm1);
                const float p11 = exp2f(sacc[nt][3] - nm1);
                sa0 += p00; sb0 += p01;
                sa1 += p10; sb1 += p11;
                sacc[nt][0] = tf32f(p00);
                sacc[nt][1] = tf32f(p01);
                sacc[nt][2] = tf32f(p10);
                sacc[nt][3] = tf32f(p11);
            }
            float ss0 = sa0 + sb0, ss1 = sa1 + sb1;
            ss0 += __shfl_xor_sync(0xffffffffu, ss0, 1);
            ss0 += __shfl_xor_sync(0xffffffffu, ss0, 2);
            ss1 += __shfl_xor_sync(0xffffffffu, ss1, 1);
            ss1 += __shfl_xor_sync(0xffffffffu, ss1, 2);

            l0 = l0 * cr0 + ss0;
            l1 = l1 * cr1 + ss1;
            m0 = nm0;
            m1 = nm1;

#pragma unroll
            for (int nt = 0; nt < 8; nt++) {
                oacc[nt][0] *= cr0; oacc[nt][1] *= cr0;
                oacc[nt][2] *= cr1; oacc[nt][3] *= cr1;
            }
        }

#pragma unroll
        for (int s2 = 0; s2 < 16; s2++) {
            uint32_t pf[4];
            pf[0] = __float_as_uint(sacc[s2][0]);
            pf[1] = __float_as_uint(sacc[s2][2]);
            pf[2] = __float_as_uint(sacc[s2][1]);
            pf[3] = __float_as_uint(sacc[s2][3]);
            const int vr0 = (s2 * 8 + kc) * VST;
#pragma unroll
            for (int nt = 0; nt < 8; nt++) {
                const int cc = nt * 8 + li;
                uint32_t bf[2];
                bf[0] = __float_as_uint(Vb[vr0 + cc]);
                bf[1] = __float_as_uint(Vb[vr0 + VST + cc]);
                MMA_TF32(oacc[nt], pf, bf);
            }
        }
    }

    // ---- finalize: /l, write ctx (tf32-rounded for the Wo GEMM) ----
    const float inv0 = 1.f / l0;
    const float inv1 = 1.f / l1;
    float* Cg0 = g_C + ((size_t)b * SS + q0 + r) * DD + h * HDD;
    float* Cg1 = g_C + ((size_t)b * SS + q0 + r + 8) * DD + h * HDD;
#pragma unroll
    for (int nt = 0; nt < 8; nt++) {
        const int c = nt * 8 + kc;
        *(float2*)&Cg0[c] = make_float2(tf32f(oacc[nt][0] * inv0),
                                        tf32f(oacc[nt][1] * inv0));
        *(float2*)&Cg1[c] = make_float2(tf32f(oacc[nt][2] * inv1),
                                        tf32f(oacc[nt][3] * inv1));
    }
}

// ---------------------------------------------------------------------------
// Launch: pre-round inputs -> QKV GEMMs -> attention -> out GEMM
// ---------------------------------------------------------------------------
extern "C" void kernel_launch(void* const* d_in, const int* in_sizes, int n_in,
                              void* d_out, int out_size)
{
    (void)in_sizes; (void)n_in; (void)out_size;
    const float* x  = (const float*)d_in[0];
    const float* Wq = (const float*)d_in[1];
    const float* bq = (const float*)d_in[2];
    const float* Wk = (const float*)d_in[3];
    const float* bk = (const float*)d_in[4];
    const float* Wv = (const float*)d_in[5];
    const float* bv = (const float*)d_in[6];
    const float* Wo = (const float*)d_in[7];
    const float* bo = (const float*)d_in[8];
    float* out = (float*)d_out;

    float *qp, *kp, *vp, *cp, *xr, *wqr, *wkr, *wvr, *wor;
    cudaGetSymbolAddress((void**)&qp, g_Q);
    cudaGetSymbolAddress((void**)&kp, g_K);
    cudaGetSymbolAddress((void**)&vp, g_V);
    cudaGetSymbolAddress((void**)&cp, g_C);
    cudaGetSymbolAddress((void**)&xr, g_Xr);
    cudaGetSymbolAddress((void**)&wqr, g_Wqr);
    cudaGetSymbolAddress((void**)&wkr, g_Wkr);
    cudaGetSymbolAddress((void**)&wvr, g_Wvr);
    cudaGetSymbolAddress((void**)&wor, g_Wor);

    cudaFuncSetAttribute(gemm_tf32<false>,
                         cudaFuncAttributeMaxDynamicSharedMemorySize,
                         GSM_BYTES);
    cudaFuncSetAttribute(gemm_tf32<true>,
                         cudaFuncAttributeMaxDynamicSharedMemorySize,
                         GSM_BYTES);
    cudaFuncSetAttribute(attn_tc,
                         cudaFuncAttributeMaxDynamicSharedMemorySize,
                         ATT_SMEM_BYTES);

    // pre-round inputs to tf32 (idempotent, graph-capturable)
    const int xn4 = MROWS * DD / 4;    // 1,048,576
    const int wn4 = DD * DD / 4;       // 262,144
    round_tf32_kernel<<<xn4 / 256, 256>>>(x, xr, xn4);
    round_tf32_kernel<<<wn4 / 256, 256>>>(Wq, wqr, wn4);
    round_tf32_kernel<<<wn4 / 256, 256>>>(Wk, wkr, wn4);
    round_tf32_kernel<<<wn4 / 256, 256>>>(Wv, wvr, wn4);
    round_tf32_kernel<<<wn4 / 256, 256>>>(Wo, wor, wn4);

    const dim3 gblk(256);
    const dim3 ggrid(DD / 128, MROWS / 128);   // (8, 32)

    gemm_tf32<false><<<ggrid, gblk, GSM_BYTES>>>(xr, wqr, bq, qp);
    gemm_tf32<true ><<<ggrid, gblk, GSM_BYTES>>>(xr, wkr, bk, kp);
    gemm_tf32<true ><<<ggrid, gblk, GSM_BYTES>>>(xr, wvr, bv, vp);

    attn_tc<<<dim3(SS / 128, HH, BB), 256, ATT_SMEM_BYTES>>>();

    gemm_tf32<false><<<ggrid, gblk, GSM_BYTES>>>(cp, wor, bo, out);
}